// round 5
// baseline (speedup 1.0000x reference)
#include <cuda_runtime.h>
#include <cuda_bf16.h>
#include <cstdint>
#include <math.h>

// Problem constants (fixed by the dataset)
#define GG 8
#define MM 1024
#define NN 8192          // GG*MM
#define HH 256
#define NHEADS 8
#define HDIM 32
#define FFND 1024
#define QKVD 768

// ---------------- scratch (device globals; no allocation) ----------------
__device__ float    g_deg [NN];
__device__ float    g_dinv[NN];
__device__ float    g_xw  [NN * HH];
__device__ float    g_xl  [NN * HH];
__device__ uint32_t g_adj [GG * MM * 32];
__device__ unsigned char g_dist[(size_t)GG * MM * MM];   // 8 MB
__device__ float    g_qkv [(size_t)NN * QKVD];
__device__ float    g_tmp [NN * HH];
__device__ float    g_h1  [NN * HH];
__device__ float    g_h2  [NN * HH];
__device__ float    g_y   [NN * HH];

#define AL16 __align__(16)
__device__ AL16 __nv_bfloat16 g_x_hi[NN * HH],  g_x_lo[NN * HH];
__device__ AL16 __nv_bfloat16 g_at_hi[NN * HH], g_at_lo[NN * HH];
__device__ AL16 __nv_bfloat16 g_h1_hi[NN * HH], g_h1_lo[NN * HH];
__device__ AL16 __nv_bfloat16 g_y_hi[NN * HH],  g_y_lo[NN * HH];
__device__ AL16 __nv_bfloat16 g_mid_hi[(size_t)NN * FFND], g_mid_lo[(size_t)NN * FFND];
// attention operand layouts
__device__ AL16 __nv_bfloat16 g_q_hi[NN * HH],  g_q_lo[NN * HH];
__device__ AL16 __nv_bfloat16 g_k_hi[NN * HH],  g_k_lo[NN * HH];
__device__ AL16 __nv_bfloat16 g_vt_hi[GG * NHEADS * HDIM * MM], g_vt_lo[GG * NHEADS * HDIM * MM];
// all weights split into one pool (offsets below)
__device__ AL16 __nv_bfloat16 g_whi[1376256], g_wlo[1376256];
#define OFF_GCN   0
#define OFF_QKV   65536
#define OFF_PROJ  262144
#define OFF_FFN1  327680
#define OFF_FFN2  589824
#define OFF_OFFN1 851968
#define OFF_OFFN2 1114112

// ---------------- helpers ----------------
__device__ __forceinline__ uint32_t packbf(float lo, float hi) {
    uint32_t r;
    asm("cvt.rn.bf16x2.f32 %0, %1, %2;" : "=r"(r) : "f"(hi), "f"(lo));
    return r;
}
__device__ __forceinline__ float ex2f(float x) {
    float y; asm("ex2.approx.f32 %0, %1;" : "=f"(y) : "f"(x)); return y;
}
__device__ __forceinline__ void split2(float a, float b, uint32_t& hi, uint32_t& lo) {
    uint32_t h = packbf(a, b);
    float ha = __uint_as_float(h << 16);
    float hb = __uint_as_float(h & 0xffff0000u);
    hi = h;
    lo = packbf(a - ha, b - hb);
}
#define CP16(dst, src) asm volatile("cp.async.cg.shared.global [%0], [%1], 16;\n" :: "r"(dst), "l"(src))
#define MMA16816(d, a0, a1, a2, a3, b0, b1) \
    asm volatile("mma.sync.aligned.m16n8k16.row.col.f32.bf16.bf16.f32 " \
                 "{%0,%1,%2,%3}, {%4,%5,%6,%7}, {%8,%9}, {%0,%1,%2,%3};" \
                 : "+f"(d[0]), "+f"(d[1]), "+f"(d[2]), "+f"(d[3]) \
                 : "r"(a0), "r"(a1), "r"(a2), "r"(a3), "r"(b0), "r"(b1))

// ---------------- fused splits ----------------
__global__ void split4(const float4* __restrict__ in, __nv_bfloat16* __restrict__ hi,
                       __nv_bfloat16* __restrict__ lo, int n4) {
    int i = blockIdx.x * blockDim.x + threadIdx.x;
    if (i >= n4) return;
    float4 v = in[i];
    uint32_t h0, l0, h1, l1;
    split2(v.x, v.y, h0, l0);
    split2(v.z, v.w, h1, l1);
    *(uint2*)(hi + i * 4) = make_uint2(h0, h1);
    *(uint2*)(lo + i * 4) = make_uint2(l0, l1);
}
__global__ void splitw(const float4* w0, const float4* w1, const float4* w2, const float4* w3,
                       const float4* w4, const float4* w5, const float4* w6,
                       __nv_bfloat16* __restrict__ hi, __nv_bfloat16* __restrict__ lo) {
    int i = blockIdx.x * blockDim.x + threadIdx.x;
    if (i >= 344064) return;
    const float4* src; int base;
    if      (i < 16384)  { src = w0; base = 0; }
    else if (i < 65536)  { src = w1; base = 16384; }
    else if (i < 81920)  { src = w2; base = 65536; }
    else if (i < 147456) { src = w3; base = 81920; }
    else if (i < 212992) { src = w4; base = 147456; }
    else if (i < 278528) { src = w5; base = 212992; }
    else                 { src = w6; base = 278528; }
    float4 v = src[i - base];
    uint32_t h0, l0, h1, l1;
    split2(v.x, v.y, h0, l0);
    split2(v.z, v.w, h1, l1);
    *(uint2*)(hi + (size_t)i * 4) = make_uint2(h0, h1);
    *(uint2*)(lo + (size_t)i * 4) = make_uint2(l0, l1);
}

// ---------------- GCN / graph prep ----------------
__global__ void zero_prep(float* __restrict__ deg, uint32_t* __restrict__ adj) {
    int i = blockIdx.x * blockDim.x + threadIdx.x;
    if (i < GG * MM * 32) adj[i] = 0u;
    if (i < NN) deg[i] = 0.f;
}
__global__ void edge_prep(const int* __restrict__ ei, int E, float* __restrict__ deg,
                          uint32_t* __restrict__ adj) {
    int e = blockIdx.x * blockDim.x + threadIdx.x;
    if (e >= E) return;
    int s = ei[e], d = ei[E + e];
    atomicAdd(&deg[d], 1.0f);
    if (s == d || (s >> 10) != (d >> 10)) return;
    int g = s >> 10, ls = s & 1023, ld = d & 1023;
    atomicOr(&adj[((size_t)g * MM + ls) * 32 + (ld >> 5)], 1u << (ld & 31));
    atomicOr(&adj[((size_t)g * MM + ld) * 32 + (ls >> 5)], 1u << (ls & 31));
}
__global__ void dinv_kernel(const float* __restrict__ deg, float* __restrict__ dinv) {
    int i = blockIdx.x * blockDim.x + threadIdx.x;
    if (i < NN) dinv[i] = rsqrtf(deg[i] + 1.0f);
}
__global__ void edge_scatter(const int* __restrict__ ei, int E,
                             const float* __restrict__ xw, const float* __restrict__ dinv,
                             float* __restrict__ xl) {
    int idx = blockIdx.x * blockDim.x + threadIdx.x;
    int e  = idx >> 6;
    int c4 = (idx & 63) * 4;
    if (e >= E) return;
    int s = __ldg(&ei[e]);
    int d = __ldg(&ei[E + e]);
    float w = __ldg(&dinv[s]) * __ldg(&dinv[d]);
    const float4 v = *(const float4*)&xw[(size_t)s * HH + c4];
    float* dst = &xl[(size_t)d * HH + c4];
    atomicAdd(dst + 0, v.x * w);
    atomicAdd(dst + 1, v.y * w);
    atomicAdd(dst + 2, v.z * w);
    atomicAdd(dst + 3, v.w * w);
}

// ---------------- SPD bitset BFS ----------------
__launch_bounds__(128)
__global__ void spd_kernel(const uint32_t* __restrict__ adj, unsigned char* __restrict__ dist) {
    extern __shared__ uint32_t adj_sh[];   // [1024][33]
    int g = blockIdx.x >> 3;
    const uint32_t* ga = adj + (size_t)g * MM * 32;
    for (int idx = threadIdx.x; idx < MM * 32; idx += blockDim.x) {
        int r = idx >> 5, w = idx & 31;
        adj_sh[r * 33 + w] = ga[idx];
    }
    __syncthreads();

    int i = (blockIdx.x & 7) * 128 + threadIdx.x;
    unsigned char* drow = dist + ((size_t)g * MM + i) * MM;

    uint32_t reach[32], frontier[32];
#pragma unroll
    for (int w = 0; w < 32; ++w) {
        uint32_t a = adj_sh[i * 33 + w];
        reach[w] = a; frontier[w] = a;
    }
#pragma unroll
    for (int w = 0; w < 32; ++w) {
        uint32_t f = frontier[w];
        uint32_t* dp = (uint32_t*)(drow + w * 32);
#pragma unroll
        for (int q = 0; q < 8; ++q) {
            uint32_t nib = (f >> (q * 4)) & 0xF;
            uint32_t word = 0x06060606u;
            if (nib & 1) word = (word & 0xFFFFFF00u) | 0x01u;
            if (nib & 2) word = (word & 0xFFFF00FFu) | 0x0100u;
            if (nib & 4) word = (word & 0xFF00FFFFu) | 0x010000u;
            if (nib & 8) word = (word & 0x00FFFFFFu) | 0x01000000u;
            dp[q] = word;
        }
    }
    drow[i] = 0;
    reach[i >> 5] |= 1u << (i & 31);

    for (int d = 2; d <= 5; ++d) {
        uint32_t nw[32];
#pragma unroll
        for (int w = 0; w < 32; ++w) nw[w] = 0u;
        for (int w = 0; w < 32; ++w) {
            uint32_t f = frontier[w];
            while (f) {
                int b = __ffs((int)f) - 1;
                f &= f - 1;
                const uint32_t* aj = &adj_sh[(w * 32 + b) * 33];
#pragma unroll
                for (int ww = 0; ww < 32; ++ww) nw[ww] |= aj[ww];
            }
        }
        uint32_t any = 0;
        uint32_t rep = (uint32_t)d * 0x01010101u;
#pragma unroll
        for (int w = 0; w < 32; ++w) {
            uint32_t newly = nw[w] & ~reach[w];
            frontier[w] = newly;
            reach[w] |= newly;
            any |= newly;
            if (newly) {
                uint32_t* dp = (uint32_t*)(drow + w * 32);
#pragma unroll
                for (int q = 0; q < 8; ++q) {
                    uint32_t nib = (newly >> (q * 4)) & 0xF;
                    if (nib) {
                        uint32_t m = ((nib & 1) ? 0xFFu : 0u) | ((nib & 2) ? 0xFF00u : 0u)
                                   | ((nib & 4) ? 0xFF0000u : 0u) | ((nib & 8) ? 0xFF000000u : 0u);
                        dp[q] = (dp[q] & ~m) | (rep & m);
                    }
                }
            }
        }
        if (!any) break;
    }
}

// ---------------- bf16x3 tensor-core GEMM: C = A @ W^T (+bias)(+gelu)(+res)(+dinv) ----------------
// A:[rows,K], W:[F,K] both split into hi/lo bf16. Block tile 128x128x32, 8 warps (64x32 each).
// 2 CTAs/SM for sync-bubble overlap.
template <int GELU, int RES, int OUTBF16, int DINV>
__launch_bounds__(256, 2)
__global__ void gemm_bf16(const __nv_bfloat16* __restrict__ Ahi, const __nv_bfloat16* __restrict__ Alo,
                          const __nv_bfloat16* __restrict__ Whi, const __nv_bfloat16* __restrict__ Wlo,
                          const float* __restrict__ bias, const float* __restrict__ res,
                          float* __restrict__ C, __nv_bfloat16* __restrict__ Chi,
                          __nv_bfloat16* __restrict__ Clo, float* __restrict__ C2,
                          const float* __restrict__ dinv, int K, int F) {
    extern __shared__ unsigned char smp[];
    const int STG = 40960;
    int m0 = blockIdx.x * 128, f0 = blockIdx.y * 128;
    int tid = threadIdx.x, lane = tid & 31, warp = tid >> 5;
    int g = lane >> 2, tg = lane & 3;
    int wm = (warp >> 2) * 64, wn = (warp & 3) * 32;
    uint32_t smem_base = (uint32_t)__cvta_generic_to_shared(smp);

    float acc[4][4][4];
#pragma unroll
    for (int a = 0; a < 4; ++a)
#pragma unroll
        for (int b = 0; b < 4; ++b)
#pragma unroll
            for (int c = 0; c < 4; ++c) acc[a][b][c] = 0.f;

    auto load_stage = [&](int s, int k0) {
        uint32_t db = smem_base + s * STG;
        const __nv_bfloat16* srcs[4] = {
            Ahi + (size_t)m0 * K + k0, Alo + (size_t)m0 * K + k0,
            Whi + (size_t)f0 * K + k0, Wlo + (size_t)f0 * K + k0 };
#pragma unroll
        for (int arr = 0; arr < 4; ++arr) {
            const __nv_bfloat16* bp = srcs[arr];
            uint32_t ab = db + arr * 10240;
#pragma unroll
            for (int c = 0; c < 2; ++c) {
                int t = tid + c * 256;
                int row = t >> 2, ch = t & 3;
                CP16(ab + row * 80 + ch * 16, bp + (size_t)row * K + ch * 8);
            }
        }
        asm volatile("cp.async.commit_group;\n" ::);
    };

    int nk = K >> 5;
    load_stage(0, 0);
    for (int kc = 0; kc < nk; ++kc) {
        if (kc + 1 < nk) {
            load_stage((kc + 1) & 1, (kc + 1) << 5);
            asm volatile("cp.async.wait_group 1;\n" ::);
        } else {
            asm volatile("cp.async.wait_group 0;\n" ::);
        }
        __syncthreads();

        const uint32_t* Ah = (const uint32_t*)(smp + (kc & 1) * STG);
        const uint32_t* Al = Ah + 2560;
        const uint32_t* Wh = Ah + 5120;
        const uint32_t* Wl = Ah + 7680;
#pragma unroll
        for (int ks = 0; ks < 2; ++ks) {
            int ku = ks * 8;
            uint32_t bh[4][2], bl[4][2];
#pragma unroll
            for (int nt = 0; nt < 4; ++nt) {
                int idx = (wn + nt * 8 + g) * 20 + ku + tg;
                bh[nt][0] = Wh[idx]; bh[nt][1] = Wh[idx + 4];
                bl[nt][0] = Wl[idx]; bl[nt][1] = Wl[idx + 4];
            }
#pragma unroll
            for (int mt = 0; mt < 4; ++mt) {
                int i0 = (wm + mt * 16 + g) * 20 + ku + tg;
                int i1 = i0 + 160;
                uint32_t ah0 = Ah[i0], ah1 = Ah[i1], ah2 = Ah[i0 + 4], ah3 = Ah[i1 + 4];
                uint32_t al0 = Al[i0], al1 = Al[i1], al2 = Al[i0 + 4], al3 = Al[i1 + 4];
#pragma unroll
                for (int nt = 0; nt < 4; ++nt) {
                    MMA16816(acc[mt][nt], ah0, ah1, ah2, ah3, bh[nt][0], bh[nt][1]);
                    MMA16816(acc[mt][nt], ah0, ah1, ah2, ah3, bl[nt][0], bl[nt][1]);
                    MMA16816(acc[mt][nt], al0, al1, al2, al3, bh[nt][0], bh[nt][1]);
                }
            }
        }
        __syncthreads();
    }

#pragma unroll
    for (int mt = 0; mt < 4; ++mt) {
#pragma unroll
        for (int half = 0; half < 2; ++half) {
            int row = m0 + wm + mt * 16 + g + half * 8;
            float di2 = 0.f;
            if (DINV) { float di = dinv[row]; di2 = di * di; }
#pragma unroll
            for (int nt = 0; nt < 4; ++nt) {
                int col = f0 + wn + nt * 8 + tg * 2;
                float v0 = acc[mt][nt][half * 2 + 0];
                float v1 = acc[mt][nt][half * 2 + 1];
                if (DINV) {
                    // raw product for edge_scatter
                    float2 r2; r2.x = v0; r2.y = v1;
                    *(float2*)(C2 + (size_t)row * F + col) = r2;
                    v0 = v0 * di2 + bias[col];
                    v1 = v1 * di2 + bias[col + 1];
                } else {
                    if (bias) { v0 += bias[col]; v1 += bias[col + 1]; }
                }
                if (GELU) { v0 = v0 * normcdff(v0); v1 = v1 * normcdff(v1); }
                if (RES)  { v0 += res[(size_t)row * F + col]; v1 += res[(size_t)row * F + col + 1]; }
                if (OUTBF16) {
                    uint32_t h, l;
                    split2(v0, v1, h, l);
                    *(uint32_t*)(Chi + (size_t)row * F + col) = h;
                    *(uint32_t*)(Clo + (size_t)row * F + col) = l;
                } else {
                    float2 o; o.x = v0; o.y = v1;
                    *(float2*)(C + (size_t)row * F + col) = o;
                }
            }
        }
    }
}

// ---------------- qkv prepass: split q(prescaled)/k, transpose v ----------------
__launch_bounds__(256)
__global__ void qkv_prep(const float* __restrict__ qkv,
                         __nv_bfloat16* __restrict__ qh, __nv_bfloat16* __restrict__ ql,
                         __nv_bfloat16* __restrict__ kh, __nv_bfloat16* __restrict__ kl,
                         __nv_bfloat16* __restrict__ vth, __nv_bfloat16* __restrict__ vtl) {
    __shared__ float vsm[64][33];
    int nb = blockIdx.x * 64;
    int g = nb >> 10;
    int jb = nb & 1023;
    int tid = threadIdx.x;
    const float scale = 0.17677669529663687f;

#pragma unroll
    for (int it = 0; it < 32; ++it) {
        int flat = tid + it * 256;
        int row = flat >> 7, c4 = flat & 127;
        int node = nb + row;
        float4 v = *(const float4*)&qkv[(size_t)node * QKVD + c4 * 4];
        int c = c4 * 4;
        uint32_t h0, l0, h1, l1;
        if (c < 256) {
            split2(v.x * scale, v.y * scale, h0, l0);
            split2(v.z * scale, v.w * scale, h1, l1);
            *(uint2*)(qh + (size_t)node * HH + c) = make_uint2(h0, h1);
            *(uint2*)(ql + (size_t)node * HH + c) = make_uint2(l0, l1);
        } else {
            split2(v.x, v.y, h0, l0);
            split2(v.z, v.w, h1, l1);
            *(uint2*)(kh + (size_t)node * HH + c - 256) = make_uint2(h0, h1);
            *(uint2*)(kl + (size_t)node * HH + c - 256) = make_uint2(l0, l1);
        }
    }

    for (int h = 0; h < NHEADS; ++h) {
        __syncthreads();
#pragma unroll
        for (int it = 0; it < 2; ++it) {
            int flat = tid + it * 256;
            int row = flat >> 3, c4 = flat & 7;
            float4 v = *(const float4*)&qkv[(size_t)(nb + row) * QKVD + 512 + h * 32 + c4 * 4];
            vsm[row][c4 * 4 + 0] = v.x;
            vsm[row][c4 * 4 + 1] = v.y;
            vsm[row][c4 * 4 + 2] = v.z;
            vsm[row][c4 * 4 + 3] = v.w;
        }
        __syncthreads();
        int d = tid >> 3, j0 = (tid & 7) * 8;
        uint32_t hw[4], lw[4];
#pragma unroll
        for (int p = 0; p < 4; ++p) {
            float a = vsm[j0 + p * 2 + 0][d];
            float b = vsm[j0 + p * 2 + 1][d];
            split2(a, b, hw[p], lw[p]);
        }
        size_t off = ((size_t)(g * NHEADS + h) * HDIM + d) * MM + jb + j0;
        *(uint4*)(vth + off) = make_uint4(hw[0], hw[1], hw[2], hw[3]);
        *(uint4*)(vtl + off) = make_uint4(lw[0], lw[1], lw[2], lw[3]);
    }
}

// ---------------- tensor-core flash attention (mma.sync) ----------------
__launch_bounds__(256)
__global__ void attn_mma(const __nv_bfloat16* __restrict__ qh, const __nv_bfloat16* __restrict__ ql,
                         const __nv_bfloat16* __restrict__ kh, const __nv_bfloat16* __restrict__ kl,
                         const __nv_bfloat16* __restrict__ vth, const __nv_bfloat16* __restrict__ vtl,
                         const unsigned char* __restrict__ dist, const float* __restrict__ bias_emb,
                         __nv_bfloat16* __restrict__ ohi, __nv_bfloat16* __restrict__ olo) {
    extern __shared__ unsigned char smp[];
    const int STG = 37888;
    __shared__ float btab[8];
    int gh = blockIdx.x;
    int g = gh >> 3, h = gh & 7;
    int i0 = blockIdx.y * 128;
    int tid = threadIdx.x, lane = tid & 31, warp = tid >> 5;
    int r = lane >> 2, tg = lane & 3;
    if (tid < 7) btab[tid] = bias_emb[tid];
    uint32_t sb = (uint32_t)__cvta_generic_to_shared(smp);
    const float L2E = 1.44269504f;

    int rowA = i0 + warp * 16 + r;
    int rowB = rowA + 8;
    uint32_t qfh[2][4], qfl[2][4];
#pragma unroll
    for (int kc = 0; kc < 2; ++kc) {
        size_t baseA = (size_t)(g * MM + rowA) * HH + h * HDIM + kc * 16 + tg * 2;
        size_t baseB = (size_t)(g * MM + rowB) * HH + h * HDIM + kc * 16 + tg * 2;
        qfh[kc][0] = *(const uint32_t*)(qh + baseA);
        qfh[kc][1] = *(const uint32_t*)(qh + baseB);
        qfh[kc][2] = *(const uint32_t*)(qh + baseA + 8);
        qfh[kc][3] = *(const uint32_t*)(qh + baseB + 8);
        qfl[kc][0] = *(const uint32_t*)(ql + baseA);
        qfl[kc][1] = *(const uint32_t*)(ql + baseB);
        qfl[kc][2] = *(const uint32_t*)(ql + baseA + 8);
        qfl[kc][3] = *(const uint32_t*)(ql + baseB + 8);
    }

    float acc_o[4][4];
#pragma unroll
    for (int a = 0; a < 4; ++a)
#pragma unroll
        for (int b = 0; b < 4; ++b) acc_o[a][b] = 0.f;
    float mA = -1e30f, mB = -1e30f, lA = 0.f, lB = 0.f;

    const unsigned char* drowA = dist + ((size_t)(g * MM + rowA)) * MM;
    const unsigned char* drowB = dist + ((size_t)(g * MM + rowB)) * MM;

    auto load_stage = [&](int s, int j0) {
        uint32_t db = sb + s * STG;
#pragma unroll
        for (int c = 0; c < 2; ++c) {
            int t = tid + c * 256;
            int row = t >> 2, ch = t & 3;
            const __nv_bfloat16* src = kh + (size_t)(g * MM + j0 + row) * HH + h * HDIM + ch * 8;
            CP16(db + row * 80 + ch * 16, src);
            const __nv_bfloat16* srcl = kl + (size_t)(g * MM + j0 + row) * HH + h * HDIM + ch * 8;
            CP16(db + 10240 + row * 80 + ch * 16, srcl);
        }
#pragma unroll
        for (int c = 0; c < 2; ++c) {
            int t = tid + c * 256;
            int row = t >> 4, ch = t & 15;
            size_t off = ((size_t)(gh) * HDIM + row) * MM + j0 + ch * 8;
            CP16(db + 20480 + row * 272 + ch * 16, vth + off);
            CP16(db + 29184 + row * 272 + ch * 16, vtl + off);
        }
        asm volatile("cp.async.commit_group;\n" ::);
    };

    load_stage(0, 0);
    for (int ch = 0; ch < 8; ++ch) {
        int j0 = ch * 128;
        if (ch < 7) {
            load_stage((ch + 1) & 1, j0 + 128);
            asm volatile("cp.async.wait_group 1;\n" ::);
        } else {
            asm volatile("cp.async.wait_group 0;\n" ::);
        }
        __syncthreads();

        const uint32_t* KH = (const uint32_t*)(smp + (ch & 1) * STG);
        const uint32_t* KL = KH + 2560;
        const uint32_t* VH = KH + 5120;
        const uint32_t* VL = VH + 2176;

        float acc_s[16][4];
#pragma unroll
        for (int nt = 0; nt < 16; ++nt)
#pragma unroll
            for (int c = 0; c < 4; ++c) acc_s[nt][c] = 0.f;
#pragma unroll
        for (int kc = 0; kc < 2; ++kc) {
#pragma unroll
            for (int nt = 0; nt < 16; ++nt) {
                int idx = (nt * 8 + r) * 20 + kc * 8 + tg;
                uint32_t b0h = KH[idx], b1h = KH[idx + 4];
                uint32_t b0l = KL[idx], b1l = KL[idx + 4];
                MMA16816(acc_s[nt], qfh[kc][0], qfh[kc][1], qfh[kc][2], qfh[kc][3], b0h, b1h);
                MMA16816(acc_s[nt], qfh[kc][0], qfh[kc][1], qfh[kc][2], qfh[kc][3], b0l, b1l);
                MMA16816(acc_s[nt], qfl[kc][0], qfl[kc][1], qfl[kc][2], qfl[kc][3], b0h, b1h);
            }
        }

        float cmA = -1e30f, cmB = -1e30f;
#pragma unroll
        for (int nt = 0; nt < 16; ++nt) {
            uchar2 dA = *(const uchar2*)(drowA + j0 + nt * 8 + tg * 2);
            uchar2 dB = *(const uchar2*)(drowB + j0 + nt * 8 + tg * 2);
            acc_s[nt][0] += btab[dA.x];
            acc_s[nt][1] += btab[dA.y];
            acc_s[nt][2] += btab[dB.x];
            acc_s[nt][3] += btab[dB.y];
            cmA = fmaxf(cmA, fmaxf(acc_s[nt][0], acc_s[nt][1]));
            cmB = fmaxf(cmB, fmaxf(acc_s[nt][2], acc_s[nt][3]));
        }
        cmA = fmaxf(cmA, __shfl_xor_sync(0xFFFFFFFFu, cmA, 1));
        cmA = fmaxf(cmA, __shfl_xor_sync(0xFFFFFFFFu, cmA, 2));
        cmB = fmaxf(cmB, __shfl_xor_sync(0xFFFFFFFFu, cmB, 1));
        cmB = fmaxf(cmB, __shfl_xor_sync(0xFFFFFFFFu, cmB, 2));

        float mAn = fmaxf(mA, cmA), mBn = fmaxf(mB, cmB);
        float corrA = ex2f((mA - mAn) * L2E);
        float corrB = ex2f((mB - mBn) * L2E);
        mA = mAn; mB = mBn;

        uint32_t ph0[16], ph1[16], pl0[16], pl1[16];
        float lsA = 0.f, lsB = 0.f;
#pragma unroll
        for (int nt = 0; nt < 16; ++nt) {
            float p0 = ex2f((acc_s[nt][0] - mA) * L2E);
            float p1 = ex2f((acc_s[nt][1] - mA) * L2E);
            float p2 = ex2f((acc_s[nt][2] - mB) * L2E);
            float p3 = ex2f((acc_s[nt][3] - mB) * L2E);
            lsA += p0 + p1; lsB += p2 + p3;
            split2(p0, p1, ph0[nt], pl0[nt]);
            split2(p2, p3, ph1[nt], pl1[nt]);
        }
        lsA += __shfl_xor_sync(0xFFFFFFFFu, lsA, 1);
        lsA += __shfl_xor_sync(0xFFFFFFFFu, lsA, 2);
        lsB += __shfl_xor_sync(0xFFFFFFFFu, lsB, 1);
        lsB += __shfl_xor_sync(0xFFFFFFFFu, lsB, 2);
        lA = lA * corrA + lsA;
        lB = lB * corrB + lsB;

#pragma unroll
        for (int nto = 0; nto < 4; ++nto) {
            acc_o[nto][0] *= corrA; acc_o[nto][1] *= corrA;
            acc_o[nto][2] *= corrB; acc_o[nto][3] *= corrB;
        }

#pragma unroll
        for (int kc = 0; kc < 8; ++kc) {
            uint32_t a0 = ph0[2 * kc], a1 = ph1[2 * kc], a2 = ph0[2 * kc + 1], a3 = ph1[2 * kc + 1];
            uint32_t c0 = pl0[2 * kc], c1 = pl1[2 * kc], c2 = pl0[2 * kc + 1], c3 = pl1[2 * kc + 1];
#pragma unroll
            for (int nto = 0; nto < 4; ++nto) {
                int idx = (nto * 8 + r) * 68 + kc * 8 + tg;
                uint32_t b0h = VH[idx], b1h = VH[idx + 4];
                uint32_t b0l = VL[idx], b1l = VL[idx + 4];
                MMA16816(acc_o[nto], a0, a1, a2, a3, b0h, b1h);
                MMA16816(acc_o[nto], a0, a1, a2, a3, b0l, b1l);
                MMA16816(acc_o[nto], c0, c1, c2, c3, b0h, b1h);
            }
        }
        __syncthreads();
    }

    float invA = 1.f / lA, invB = 1.f / lB;
#pragma unroll
    for (int nto = 0; nto < 4; ++nto) {
        int col = h * HDIM + nto * 8 + tg * 2;
        float a0 = acc_o[nto][0] * invA, a1 = acc_o[nto][1] * invA;
        float b0 = acc_o[nto][2] * invB, b1 = acc_o[nto][3] * invB;
        uint32_t hA, lA2, hB, lB2;
        split2(a0, a1, hA, lA2);
        split2(b0, b1, hB, lB2);
        *(uint32_t*)(ohi + (size_t)(g * MM + rowA) * HH + col) = hA;
        *(uint32_t*)(olo + (size_t)(g * MM + rowA) * HH + col) = lA2;
        *(uint32_t*)(ohi + (size_t)(g * MM + rowB) * HH + col) = hB;
        *(uint32_t*)(olo + (size_t)(g * MM + rowB) * HH + col) = lB2;
    }
}

// ---------------- LayerNorm (up to 3 summed inputs) ----------------
__launch_bounds__(256)
__global__ void ln_kernel(const float* __restrict__ a, const float* __restrict__ b,
                          const float* __restrict__ c, const float* __restrict__ gam,
                          const float* __restrict__ bet, float* __restrict__ out,
                          __nv_bfloat16* __restrict__ ohi, __nv_bfloat16* __restrict__ olo) {
    int row = blockIdx.x, t = threadIdx.x;
    size_t idx = (size_t)row * HH + t;
    float v = a[idx];
    if (b) v += b[idx];
    if (c) v += c[idx];
    float s = v, s2 = v * v;
#pragma unroll
    for (int o = 16; o; o >>= 1) {
        s  += __shfl_xor_sync(0xFFFFFFFFu, s, o);
        s2 += __shfl_xor_sync(0xFFFFFFFFu, s2, o);
    }
    __shared__ float sh1[8], sh2[8];
    int w = t >> 5, ln = t & 31;
    if (ln == 0) { sh1[w] = s; sh2[w] = s2; }
    __syncthreads();
    if (w == 0) {
        s  = (ln < 8) ? sh1[ln] : 0.f;
        s2 = (ln < 8) ? sh2[ln] : 0.f;
#pragma unroll
        for (int o = 4; o; o >>= 1) {
            s  += __shfl_xor_sync(0xFFFFFFFFu, s, o);
            s2 += __shfl_xor_sync(0xFFFFFFFFu, s2, o);
        }
        if (ln == 0) { sh1[0] = s; sh2[0] = s2; }
    }
    __syncthreads();
    float mean = sh1[0] * (1.f / HH);
    float var  = sh2[0] * (1.f / HH) - mean * mean;
    float rr = (v - mean) * rsqrtf(var + 1e-5f) * gam[t] + bet[t];
    out[idx] = rr;
    if (ohi) {
        __nv_bfloat16 hh = __float2bfloat16(rr);
        ohi[idx] = hh;
        olo[idx] = __float2bfloat16(rr - __bfloat162float(hh));
    }
}

// ---------------- host ----------------
static void* sym(const void* s) { void* p = nullptr; cudaGetSymbolAddress(&p, s); return p; }

extern "C" void kernel_launch(void* const* d_in, const int* in_sizes, int n_in,
                              void* d_out, int out_size) {
    const float* x      = (const float*)d_in[0];
    const float* gcn_w  = (const float*)d_in[1];
    const float* gcn_b  = (const float*)d_in[2];
    const float* qkv_w  = (const float*)d_in[3];
    const float* qkv_b  = (const float*)d_in[4];
    const float* proj_w = (const float*)d_in[5];
    const float* proj_b = (const float*)d_in[6];
    const float* ln1_g  = (const float*)d_in[7];
    const float* ln1_b  = (const float*)d_in[8];
    const float* ln2_g  = (const float*)d_in[9];
    const float* ln2_b  = (const float*)d_in[10];
    const float* ffn1_w = (const float*)d_in[11];
    const float* ffn1_b = (const float*)d_in[12];
    const float* ffn2_w = (const float*)d_in[13];
    const float* ffn2_b = (const float*)d_in[14];
    const float* bias_e = (const float*)d_in[15];
    const float* oln1_g = (const float*)d_in[16];
    const float* oln1_b = (const float*)d_in[17];
    const float* oln2_g = (const float*)d_in[18];
    const float* oln2_b = (const float*)d_in[19];
    const float* offn1_w= (const float*)d_in[20];
    const float* offn1_b= (const float*)d_in[21];
    const float* offn2_w= (const float*)d_in[22];
    const float* offn2_b= (const float*)d_in[23];
    const int*   ei     = (const int*)d_in[24];
    int E = in_sizes[24] / 2;

    float*    p_deg  = (float*)sym(g_deg);
    float*    p_dinv = (float*)sym(g_dinv);
    float*    p_xw   = (float*)sym(g_xw);
    float*    p_xl   = (float*)sym(g_xl);
    uint32_t* p_adj  = (uint32_t*)sym(g_adj);
    unsigned char* p_dist = (unsigned char*)sym(g_dist);
    float*    p_qkv  = (float*)sym(g_qkv);
    float*    p_tmp  = (float*)sym(g_tmp);
    float*    p_h1   = (float*)sym(g_h1);
    float*    p_h2   = (float*)sym(g_h2);
    float*    p_y    = (float*)sym(g_y);
    __nv_bfloat16* x_hi  = (__nv_bfloat16*)sym(g_x_hi);
    __nv_bfloat16* x_lo  = (__nv_bfloat16*)sym(g_x_lo);
    __nv_bfloat16* at_hi = (__nv_bfloat16*)sym(g_at_hi);
    __nv_bfloat16* at_lo = (__nv_bfloat16*)sym(g_at_lo);
    __nv_bfloat16* h1_hi = (__nv_bfloat16*)sym(g_h1_hi);
    __nv_bfloat16* h1_lo = (__nv_bfloat16*)sym(g_h1_lo);
    __nv_bfloat16* y_hi  = (__nv_bfloat16*)sym(g_y_hi);
    __nv_bfloat16* y_lo  = (__nv_bfloat16*)sym(g_y_lo);
    __nv_bfloat16* mid_hi= (__nv_bfloat16*)sym(g_mid_hi);
    __nv_bfloat16* mid_lo= (__nv_bfloat16*)sym(g_mid_lo);
    __nv_bfloat16* q_hi  = (__nv_bfloat16*)sym(g_q_hi);
    __nv_bfloat16* q_lo  = (__nv_bfloat16*)sym(g_q_lo);
    __nv_bfloat16* k_hi  = (__nv_bfloat16*)sym(g_k_hi);
    __nv_bfloat16* k_lo  = (__nv_bfloat16*)sym(g_k_lo);
    __nv_bfloat16* vt_hi = (__nv_bfloat16*)sym(g_vt_hi);
    __nv_bfloat16* vt_lo = (__nv_bfloat16*)sym(g_vt_lo);
    __nv_bfloat16* whi   = (__nv_bfloat16*)sym(g_whi);
    __nv_bfloat16* wlo   = (__nv_bfloat16*)sym(g_wlo);
    float* out = (float*)d_out;

    const int SMEM = 81920;
    const int ASMEM = 75776;
    cudaFuncSetAttribute(gemm_bf16<0,0,0,0>, cudaFuncAttributeMaxDynamicSharedMemorySize, SMEM);
    cudaFuncSetAttribute(gemm_bf16<0,1,0,0>, cudaFuncAttributeMaxDynamicSharedMemorySize, SMEM);
    cudaFuncSetAttribute(gemm_bf16<1,0,1,0>, cudaFuncAttributeMaxDynamicSharedMemorySize, SMEM);
    cudaFuncSetAttribute(gemm_bf16<0,0,0,1>, cudaFuncAttributeMaxDynamicSharedMemorySize, SMEM);
    cudaFuncSetAttribute(attn_mma, cudaFuncAttributeMaxDynamicSharedMemorySize, ASMEM);
    cudaFuncSetAttribute(spd_kernel, cudaFuncAttributeMaxDynamicSharedMemorySize, MM * 33 * 4);

    // launches 1-4: prep (ncu -s 5 lands on the QKV GEMM below)
    split4<<<(NN * HH / 4 + 255) / 256, 256>>>((const float4*)x, x_hi, x_lo, NN * HH / 4);
    splitw<<<(344064 + 255) / 256, 256>>>((const float4*)gcn_w, (const float4*)qkv_w,
        (const float4*)proj_w, (const float4*)ffn1_w, (const float4*)ffn2_w,
        (const float4*)offn1_w, (const float4*)offn2_w, whi, wlo);
    zero_prep<<<(GG * MM * 32 + 255) / 256, 256>>>(p_deg, p_adj);
    edge_prep<<<(E + 255) / 256, 256>>>(ei, E, p_deg, p_adj);

    // launch 5: QKV GEMM (profiled)
    gemm_bf16<0,0,0,0><<<dim3(NN/128, QKVD/128), 256, SMEM>>>(x_hi, x_lo, whi + OFF_QKV, wlo + OFF_QKV,
        qkv_b, nullptr, p_qkv, nullptr, nullptr, nullptr, nullptr, HH, QKVD);

    // --- GCN branch (fused dinv epilogue) ---
    dinv_kernel<<<NN / 256, 256>>>(p_deg, p_dinv);
    gemm_bf16<0,0,0,1><<<dim3(NN/128, HH/128), 256, SMEM>>>(x_hi, x_lo, whi + OFF_GCN, wlo + OFF_GCN,
        gcn_b, nullptr, p_xl, nullptr, nullptr, p_xw, p_dinv, HH, HH);
    edge_scatter<<<(E * 64 + 255) / 256, 256>>>(ei, E, p_xw, p_dinv, p_xl);
    spd_kernel<<<64, 128, MM * 33 * 4>>>(p_adj, p_dist);

    // --- Graphormer layer ---
    qkv_prep<<<NN / 64, 256>>>(p_qkv, q_hi, q_lo, k_hi, k_lo, vt_hi, vt_lo);
    attn_mma<<<dim3(GG * NHEADS, MM / 128), 256, ASMEM>>>(q_hi, q_lo, k_hi, k_lo, vt_hi, vt_lo,
        p_dist, bias_e, at_hi, at_lo);
    gemm_bf16<0,1,0,0><<<dim3(NN/128, HH/128), 256, SMEM>>>(at_hi, at_lo, whi + OFF_PROJ, wlo + OFF_PROJ,
        proj_b, x, p_tmp, nullptr, nullptr, nullptr, nullptr, HH, HH);
    ln_kernel<<<NN, 256>>>(p_tmp, nullptr, nullptr, ln1_g, ln1_b, p_h1, h1_hi, h1_lo);
    gemm_bf16<1,0,1,0><<<dim3(NN/128, FFND/128), 256, SMEM>>>(h1_hi, h1_lo, whi + OFF_FFN1, wlo + OFF_FFN1,
        ffn1_b, nullptr, nullptr, mid_hi, mid_lo, nullptr, nullptr, HH, FFND);
    gemm_bf16<0,1,0,0><<<dim3(NN/128, HH/128), 256, SMEM>>>(mid_hi, mid_lo, whi + OFF_FFN2, wlo + OFF_FFN2,
        ffn2_b, p_h1, p_tmp, nullptr, nullptr, nullptr, nullptr, FFND, HH);
    ln_kernel<<<NN, 256>>>(p_tmp, nullptr, nullptr, ln2_g, ln2_b, p_h2, nullptr, nullptr);

    // --- GPS combine + outer FFN ---
    ln_kernel<<<NN, 256>>>(x, p_xl, p_h2, oln1_g, oln1_b, p_y, y_hi, y_lo);
    gemm_bf16<1,0,1,0><<<dim3(NN/128, FFND/128), 256, SMEM>>>(y_hi, y_lo, whi + OFF_OFFN1, wlo + OFF_OFFN1,
        offn1_b, nullptr, nullptr, mid_hi, mid_lo, nullptr, nullptr, HH, FFND);
    gemm_bf16<0,1,0,0><<<dim3(NN/128, HH/128), 256, SMEM>>>(mid_hi, mid_lo, whi + OFF_OFFN2, wlo + OFF_OFFN2,
        offn2_b, p_y, p_tmp, nullptr, nullptr, nullptr, nullptr, FFND, HH);
    ln_kernel<<<NN, 256>>>(p_tmp, nullptr, nullptr, oln2_g, oln2_b, out, nullptr, nullptr);
}

// round 6
// speedup vs baseline: 1.0612x; 1.0612x over previous
#include <cuda_runtime.h>
#include <cuda_fp16.h>
#include <cstdint>
#include <math.h>

// Problem constants (fixed by the dataset)
#define GG 8
#define MM 1024
#define NN 8192          // GG*MM
#define HH 256
#define NHEADS 8
#define HDIM 32
#define FFND 1024
#define QKVD 768

// ---------------- scratch (device globals; no allocation) ----------------
__device__ float    g_deg [NN];
__device__ float    g_dinv[NN];
__device__ float    g_xw  [NN * HH];
__device__ float    g_xl  [NN * HH];
__device__ uint32_t g_adj [GG * MM * 32];
__device__ unsigned char g_dist[(size_t)GG * MM * MM];   // 8 MB
__device__ float    g_qkv [(size_t)NN * QKVD];
__device__ float    g_tmp [NN * HH];
__device__ float    g_h1  [NN * HH];
__device__ float    g_h2  [NN * HH];
__device__ float    g_y   [NN * HH];

#define AL16 __align__(16)
// activations: single fp16 (A-operands)
__device__ AL16 __half g_x_h [NN * HH];
__device__ AL16 __half g_at_h[NN * HH];
__device__ AL16 __half g_h1_h[NN * HH];
__device__ AL16 __half g_y_h [NN * HH];
__device__ AL16 __half g_mid_h[(size_t)NN * FFND];
// attention operands
__device__ AL16 __half g_q_h [NN * HH];
__device__ AL16 __half g_k_h [NN * HH], g_k_l [NN * HH];
__device__ AL16 __half g_vt_h[GG * NHEADS * HDIM * MM], g_vt_l[GG * NHEADS * HDIM * MM];
// weights: dual fp16 (B-operands), one pool
__device__ AL16 __half g_whi[1376256], g_wlo[1376256];
#define OFF_GCN   0
#define OFF_QKV   65536
#define OFF_PROJ  262144
#define OFF_FFN1  327680
#define OFF_FFN2  589824
#define OFF_OFFN1 851968
#define OFF_OFFN2 1114112

// ---------------- helpers ----------------
__device__ __forceinline__ uint32_t packh(float a, float b) {   // a->low, b->high
    uint32_t r;
    asm("cvt.rn.f16x2.f32 %0, %1, %2;" : "=r"(r) : "f"(b), "f"(a));
    return r;
}
__device__ __forceinline__ float ex2f(float x) {
    float y; asm("ex2.approx.f32 %0, %1;" : "=f"(y) : "f"(x)); return y;
}
__device__ __forceinline__ void split2(float a, float b, uint32_t& hi, uint32_t& lo) {
    uint32_t h = packh(a, b);
    __half2 h2 = *reinterpret_cast<__half2*>(&h);
    float2 f2 = __half22float2(h2);
    hi = h;
    lo = packh(a - f2.x, b - f2.y);
}
#define CP16(dst, src) asm volatile("cp.async.cg.shared.global [%0], [%1], 16;\n" :: "r"(dst), "l"(src))
#define MMAH(d, a0, a1, a2, a3, b0, b1) \
    asm volatile("mma.sync.aligned.m16n8k16.row.col.f32.f16.f16.f32 " \
                 "{%0,%1,%2,%3}, {%4,%5,%6,%7}, {%8,%9}, {%0,%1,%2,%3};" \
                 : "+f"(d[0]), "+f"(d[1]), "+f"(d[2]), "+f"(d[3]) \
                 : "r"(a0), "r"(a1), "r"(a2), "r"(a3), "r"(b0), "r"(b1))

// ---------------- splits ----------------
__global__ void splitx(const float4* __restrict__ in, __half* __restrict__ hi, int n4) {
    int i = blockIdx.x * blockDim.x + threadIdx.x;
    if (i >= n4) return;
    float4 v = in[i];
    *(uint2*)(hi + i * 4) = make_uint2(packh(v.x, v.y), packh(v.z, v.w));
}
__global__ void splitw(const float4* w0, const float4* w1, const float4* w2, const float4* w3,
                       const float4* w4, const float4* w5, const float4* w6,
                       __half* __restrict__ hi, __half* __restrict__ lo) {
    int i = blockIdx.x * blockDim.x + threadIdx.x;
    if (i >= 344064) return;
    const float4* src; int base;
    if      (i < 16384)  { src = w0; base = 0; }
    else if (i < 65536)  { src = w1; base = 16384; }
    else if (i < 81920)  { src = w2; base = 65536; }
    else if (i < 147456) { src = w3; base = 81920; }
    else if (i < 212992) { src = w4; base = 147456; }
    else if (i < 278528) { src = w5; base = 212992; }
    else                 { src = w6; base = 278528; }
    float4 v = src[i - base];
    uint32_t h0, l0, h1, l1;
    split2(v.x, v.y, h0, l0);
    split2(v.z, v.w, h1, l1);
    *(uint2*)(hi + (size_t)i * 4) = make_uint2(h0, h1);
    *(uint2*)(lo + (size_t)i * 4) = make_uint2(l0, l1);
}

// ---------------- GCN / graph prep ----------------
__global__ void zero_prep(float* __restrict__ deg, uint32_t* __restrict__ adj) {
    int i = blockIdx.x * blockDim.x + threadIdx.x;
    if (i < GG * MM * 32) adj[i] = 0u;
    if (i < NN) deg[i] = 0.f;
}
__global__ void edge_prep(const int* __restrict__ ei, int E, float* __restrict__ deg,
                          uint32_t* __restrict__ adj) {
    int e = blockIdx.x * blockDim.x + threadIdx.x;
    if (e >= E) return;
    int s = ei[e], d = ei[E + e];
    atomicAdd(&deg[d], 1.0f);
    if (s == d || (s >> 10) != (d >> 10)) return;
    int g = s >> 10, ls = s & 1023, ld = d & 1023;
    atomicOr(&adj[((size_t)g * MM + ls) * 32 + (ld >> 5)], 1u << (ld & 31));
    atomicOr(&adj[((size_t)g * MM + ld) * 32 + (ls >> 5)], 1u << (ls & 31));
}
__global__ void dinv_kernel(const float* __restrict__ deg, float* __restrict__ dinv) {
    int i = blockIdx.x * blockDim.x + threadIdx.x;
    if (i < NN) dinv[i] = rsqrtf(deg[i] + 1.0f);
}
__global__ void edge_scatter(const int* __restrict__ ei, int E,
                             const float* __restrict__ xw, const float* __restrict__ dinv,
                             float* __restrict__ xl) {
    int idx = blockIdx.x * blockDim.x + threadIdx.x;
    int e  = idx >> 6;
    int c4 = (idx & 63) * 4;
    if (e >= E) return;
    int s = __ldg(&ei[e]);
    int d = __ldg(&ei[E + e]);
    float w = __ldg(&dinv[s]) * __ldg(&dinv[d]);
    const float4 v = *(const float4*)&xw[(size_t)s * HH + c4];
    float* dst = &xl[(size_t)d * HH + c4];
    atomicAdd(dst + 0, v.x * w);
    atomicAdd(dst + 1, v.y * w);
    atomicAdd(dst + 2, v.z * w);
    atomicAdd(dst + 3, v.w * w);
}

// ---------------- SPD bitset BFS ----------------
__launch_bounds__(128)
__global__ void spd_kernel(const uint32_t* __restrict__ adj, unsigned char* __restrict__ dist) {
    extern __shared__ uint32_t adj_sh[];   // [1024][33]
    int g = blockIdx.x >> 3;
    const uint32_t* ga = adj + (size_t)g * MM * 32;
    for (int idx = threadIdx.x; idx < MM * 32; idx += blockDim.x) {
        int r = idx >> 5, w = idx & 31;
        adj_sh[r * 33 + w] = ga[idx];
    }
    __syncthreads();

    int i = (blockIdx.x & 7) * 128 + threadIdx.x;
    unsigned char* drow = dist + ((size_t)g * MM + i) * MM;

    uint32_t reach[32], frontier[32];
#pragma unroll
    for (int w = 0; w < 32; ++w) {
        uint32_t a = adj_sh[i * 33 + w];
        reach[w] = a; frontier[w] = a;
    }
#pragma unroll
    for (int w = 0; w < 32; ++w) {
        uint32_t f = frontier[w];
        uint32_t* dp = (uint32_t*)(drow + w * 32);
#pragma unroll
        for (int q = 0; q < 8; ++q) {
            uint32_t nib = (f >> (q * 4)) & 0xF;
            uint32_t word = 0x06060606u;
            if (nib & 1) word = (word & 0xFFFFFF00u) | 0x01u;
            if (nib & 2) word = (word & 0xFFFF00FFu) | 0x0100u;
            if (nib & 4) word = (word & 0xFF00FFFFu) | 0x010000u;
            if (nib & 8) word = (word & 0x00FFFFFFu) | 0x01000000u;
            dp[q] = word;
        }
    }
    drow[i] = 0;
    reach[i >> 5] |= 1u << (i & 31);

    for (int d = 2; d <= 5; ++d) {
        uint32_t nw[32];
#pragma unroll
        for (int w = 0; w < 32; ++w) nw[w] = 0u;
        for (int w = 0; w < 32; ++w) {
            uint32_t f = frontier[w];
            while (f) {
                int b = __ffs((int)f) - 1;
                f &= f - 1;
                const uint32_t* aj = &adj_sh[(w * 32 + b) * 33];
#pragma unroll
                for (int ww = 0; ww < 32; ++ww) nw[ww] |= aj[ww];
            }
        }
        uint32_t any = 0;
        uint32_t rep = (uint32_t)d * 0x01010101u;
#pragma unroll
        for (int w = 0; w < 32; ++w) {
            uint32_t newly = nw[w] & ~reach[w];
            frontier[w] = newly;
            reach[w] |= newly;
            any |= newly;
            if (newly) {
                uint32_t* dp = (uint32_t*)(drow + w * 32);
#pragma unroll
                for (int q = 0; q < 8; ++q) {
                    uint32_t nib = (newly >> (q * 4)) & 0xF;
                    if (nib) {
                        uint32_t m = ((nib & 1) ? 0xFFu : 0u) | ((nib & 2) ? 0xFF00u : 0u)
                                   | ((nib & 4) ? 0xFF0000u : 0u) | ((nib & 8) ? 0xFF000000u : 0u);
                        dp[q] = (dp[q] & ~m) | (rep & m);
                    }
                }
            }
        }
        if (!any) break;
    }
}

// ---------------- fp16 tensor-core GEMM: C = A @ W^T, A fp16-single, W fp16-dual ----------------
// Block tile 128x128x32, 8 warps (64x32 each). 2 MMAs per fragment (W-hi, W-lo).
template <int GELU, int RES, int OUTF16, int DINV>
__launch_bounds__(256, 2)
__global__ void gemm_f16(const __half* __restrict__ Ag, const __half* __restrict__ Whg,
                         const __half* __restrict__ Wlg,
                         const float* __restrict__ bias, const float* __restrict__ res,
                         float* __restrict__ C, __half* __restrict__ Ch,
                         float* __restrict__ C2, const float* __restrict__ dinv, int K, int F) {
    extern __shared__ unsigned char smp[];
    const int STG = 30720;    // 3 arrays x 128 rows x 80B
    int m0 = blockIdx.x * 128, f0 = blockIdx.y * 128;
    int tid = threadIdx.x, lane = tid & 31, warp = tid >> 5;
    int g = lane >> 2, tg = lane & 3;
    int wm = (warp >> 2) * 64, wn = (warp & 3) * 32;
    uint32_t smem_base = (uint32_t)__cvta_generic_to_shared(smp);

    float acc[4][4][4];
#pragma unroll
    for (int a = 0; a < 4; ++a)
#pragma unroll
        for (int b = 0; b < 4; ++b)
#pragma unroll
            for (int c = 0; c < 4; ++c) acc[a][b][c] = 0.f;

    auto load_stage = [&](int s, int k0) {
        uint32_t db = smem_base + s * STG;
        const __half* srcs[3] = {
            Ag + (size_t)m0 * K + k0, Whg + (size_t)f0 * K + k0, Wlg + (size_t)f0 * K + k0 };
#pragma unroll
        for (int arr = 0; arr < 3; ++arr) {
            const __half* bp = srcs[arr];
            uint32_t ab = db + arr * 10240;
#pragma unroll
            for (int c = 0; c < 2; ++c) {
                int t = tid + c * 256;
                int row = t >> 2, ch = t & 3;
                CP16(ab + row * 80 + ch * 16, bp + (size_t)row * K + ch * 8);
            }
        }
        asm volatile("cp.async.commit_group;\n" ::);
    };

    int nk = K >> 5;
    load_stage(0, 0);
    for (int kc = 0; kc < nk; ++kc) {
        if (kc + 1 < nk) {
            load_stage((kc + 1) & 1, (kc + 1) << 5);
            asm volatile("cp.async.wait_group 1;\n" ::);
        } else {
            asm volatile("cp.async.wait_group 0;\n" ::);
        }
        __syncthreads();

        const uint32_t* As = (const uint32_t*)(smp + (kc & 1) * STG);
        const uint32_t* Wh = As + 2560;
        const uint32_t* Wl = As + 5120;
#pragma unroll
        for (int ks = 0; ks < 2; ++ks) {
            int ku = ks * 8;
            uint32_t bh[4][2], bl[4][2];
#pragma unroll
            for (int nt = 0; nt < 4; ++nt) {
                int idx = (wn + nt * 8 + g) * 20 + ku + tg;
                bh[nt][0] = Wh[idx]; bh[nt][1] = Wh[idx + 4];
                bl[nt][0] = Wl[idx]; bl[nt][1] = Wl[idx + 4];
            }
#pragma unroll
            for (int mt = 0; mt < 4; ++mt) {
                int i0 = (wm + mt * 16 + g) * 20 + ku + tg;
                int i1 = i0 + 160;
                uint32_t a0 = As[i0], a1 = As[i1], a2 = As[i0 + 4], a3 = As[i1 + 4];
#pragma unroll
                for (int nt = 0; nt < 4; ++nt) {
                    MMAH(acc[mt][nt], a0, a1, a2, a3, bh[nt][0], bh[nt][1]);
                    MMAH(acc[mt][nt], a0, a1, a2, a3, bl[nt][0], bl[nt][1]);
                }
            }
        }
        __syncthreads();
    }

#pragma unroll
    for (int mt = 0; mt < 4; ++mt) {
#pragma unroll
        for (int half = 0; half < 2; ++half) {
            int row = m0 + wm + mt * 16 + g + half * 8;
            float di2 = 0.f;
            if (DINV) { float di = dinv[row]; di2 = di * di; }
#pragma unroll
            for (int nt = 0; nt < 4; ++nt) {
                int col = f0 + wn + nt * 8 + tg * 2;
                float v0 = acc[mt][nt][half * 2 + 0];
                float v1 = acc[mt][nt][half * 2 + 1];
                if (DINV) {
                    float2 r2; r2.x = v0; r2.y = v1;
                    *(float2*)(C2 + (size_t)row * F + col) = r2;
                    v0 = v0 * di2 + bias[col];
                    v1 = v1 * di2 + bias[col + 1];
                } else {
                    if (bias) { v0 += bias[col]; v1 += bias[col + 1]; }
                }
                if (GELU) { v0 = v0 * normcdff(v0); v1 = v1 * normcdff(v1); }
                if (RES)  { v0 += res[(size_t)row * F + col]; v1 += res[(size_t)row * F + col + 1]; }
                if (OUTF16) {
                    *(uint32_t*)(Ch + (size_t)row * F + col) = packh(v0, v1);
                } else {
                    float2 o; o.x = v0; o.y = v1;
                    *(float2*)(C + (size_t)row * F + col) = o;
                }
            }
        }
    }
}

// ---------------- qkv prepass: q(prescaled) fp16, k dual, v transposed dual ----------------
__launch_bounds__(256)
__global__ void qkv_prep(const float* __restrict__ qkv,
                         __half* __restrict__ qh,
                         __half* __restrict__ kh, __half* __restrict__ kl,
                         __half* __restrict__ vth, __half* __restrict__ vtl) {
    __shared__ float vsm[64][33];
    int nb = blockIdx.x * 64;
    int g = nb >> 10;
    int jb = nb & 1023;
    int tid = threadIdx.x;
    const float scale = 0.17677669529663687f;

#pragma unroll
    for (int it = 0; it < 32; ++it) {
        int flat = tid + it * 256;
        int row = flat >> 7, c4 = flat & 127;
        int node = nb + row;
        float4 v = *(const float4*)&qkv[(size_t)node * QKVD + c4 * 4];
        int c = c4 * 4;
        if (c < 256) {
            *(uint2*)(qh + (size_t)node * HH + c) =
                make_uint2(packh(v.x * scale, v.y * scale), packh(v.z * scale, v.w * scale));
        } else {
            uint32_t h0, l0, h1, l1;
            split2(v.x, v.y, h0, l0);
            split2(v.z, v.w, h1, l1);
            *(uint2*)(kh + (size_t)node * HH + c - 256) = make_uint2(h0, h1);
            *(uint2*)(kl + (size_t)node * HH + c - 256) = make_uint2(l0, l1);
        }
    }

    for (int h = 0; h < NHEADS; ++h) {
        __syncthreads();
#pragma unroll
        for (int it = 0; it < 2; ++it) {
            int flat = tid + it * 256;
            int row = flat >> 3, c4 = flat & 7;
            float4 v = *(const float4*)&qkv[(size_t)(nb + row) * QKVD + 512 + h * 32 + c4 * 4];
            vsm[row][c4 * 4 + 0] = v.x;
            vsm[row][c4 * 4 + 1] = v.y;
            vsm[row][c4 * 4 + 2] = v.z;
            vsm[row][c4 * 4 + 3] = v.w;
        }
        __syncthreads();
        int d = tid >> 3, j0 = (tid & 7) * 8;
        uint32_t hw[4], lw[4];
#pragma unroll
        for (int p = 0; p < 4; ++p) {
            float a = vsm[j0 + p * 2 + 0][d];
            float b = vsm[j0 + p * 2 + 1][d];
            split2(a, b, hw[p], lw[p]);
        }
        size_t off = ((size_t)(g * NHEADS + h) * HDIM + d) * MM + jb + j0;
        *(uint4*)(vth + off) = make_uint4(hw[0], hw[1], hw[2], hw[3]);
        *(uint4*)(vtl + off) = make_uint4(lw[0], lw[1], lw[2], lw[3]);
    }
}

// ---------------- tensor-core flash attention (fp16, A-single / B-dual) ----------------
__launch_bounds__(256)
__global__ void attn_mma(const __half* __restrict__ qh,
                         const __half* __restrict__ kh, const __half* __restrict__ kl,
                         const __half* __restrict__ vth, const __half* __restrict__ vtl,
                         const unsigned char* __restrict__ dist, const float* __restrict__ bias_emb,
                         __half* __restrict__ oh) {
    extern __shared__ unsigned char smp[];
    const int STG = 37888;
    __shared__ float btab[8];
    int gh = blockIdx.x;
    int g = gh >> 3, h = gh & 7;
    int i0 = blockIdx.y * 128;
    int tid = threadIdx.x, lane = tid & 31, warp = tid >> 5;
    int r = lane >> 2, tg = lane & 3;
    if (tid < 7) btab[tid] = bias_emb[tid];
    uint32_t sb = (uint32_t)__cvta_generic_to_shared(smp);
    const float L2E = 1.44269504f;

    int rowA = i0 + warp * 16 + r;
    int rowB = rowA + 8;
    uint32_t qf[2][4];
#pragma unroll
    for (int kc = 0; kc < 2; ++kc) {
        size_t baseA = (size_t)(g * MM + rowA) * HH + h * HDIM + kc * 16 + tg * 2;
        size_t baseB = (size_t)(g * MM + rowB) * HH + h * HDIM + kc * 16 + tg * 2;
        qf[kc][0] = *(const uint32_t*)(qh + baseA);
        qf[kc][1] = *(const uint32_t*)(qh + baseB);
        qf[kc][2] = *(const uint32_t*)(qh + baseA + 8);
        qf[kc][3] = *(const uint32_t*)(qh + baseB + 8);
    }

    float acc_o[4][4];
#pragma unroll
    for (int a = 0; a < 4; ++a)
#pragma unroll
        for (int b = 0; b < 4; ++b) acc_o[a][b] = 0.f;
    float mA = -1e30f, mB = -1e30f, lA = 0.f, lB = 0.f;

    const unsigned char* drowA = dist + ((size_t)(g * MM + rowA)) * MM;
    const unsigned char* drowB = dist + ((size_t)(g * MM + rowB)) * MM;

    auto load_stage = [&](int s, int j0) {
        uint32_t db = sb + s * STG;
#pragma unroll
        for (int c = 0; c < 2; ++c) {
            int t = tid + c * 256;
            int row = t >> 2, ch = t & 3;
            const __half* src = kh + (size_t)(g * MM + j0 + row) * HH + h * HDIM + ch * 8;
            CP16(db + row * 80 + ch * 16, src);
            const __half* srcl = kl + (size_t)(g * MM + j0 + row) * HH + h * HDIM + ch * 8;
            CP16(db + 10240 + row * 80 + ch * 16, srcl);
        }
#pragma unroll
        for (int c = 0; c < 2; ++c) {
            int t = tid + c * 256;
            int row = t >> 4, ch = t & 15;
            size_t off = ((size_t)(gh) * HDIM + row) * MM + j0 + ch * 8;
            CP16(db + 20480 + row * 272 + ch * 16, vth + off);
            CP16(db + 29184 + row * 272 + ch * 16, vtl + off);
        }
        asm volatile("cp.async.commit_group;\n" ::);
    };

    load_stage(0, 0);
    for (int ch = 0; ch < 8; ++ch) {
        int j0 = ch * 128;
        if (ch < 7) {
            load_stage((ch + 1) & 1, j0 + 128);
            asm volatile("cp.async.wait_group 1;\n" ::);
        } else {
            asm volatile("cp.async.wait_group 0;\n" ::);
        }
        __syncthreads();

        const uint32_t* KH = (const uint32_t*)(smp + (ch & 1) * STG);
        const uint32_t* KL = KH + 2560;
        const uint32_t* VH = KH + 5120;
        const uint32_t* VL = VH + 2176;

        float acc_s[16][4];
#pragma unroll
        for (int nt = 0; nt < 16; ++nt)
#pragma unroll
            for (int c = 0; c < 4; ++c) acc_s[nt][c] = 0.f;
#pragma unroll
        for (int kc = 0; kc < 2; ++kc) {
#pragma unroll
            for (int nt = 0; nt < 16; ++nt) {
                int idx = (nt * 8 + r) * 20 + kc * 8 + tg;
                uint32_t b0h = KH[idx], b1h = KH[idx + 4];
                uint32_t b0l = KL[idx], b1l = KL[idx + 4];
                MMAH(acc_s[nt], qf[kc][0], qf[kc][1], qf[kc][2], qf[kc][3], b0h, b1h);
                MMAH(acc_s[nt], qf[kc][0], qf[kc][1], qf[kc][2], qf[kc][3], b0l, b1l);
            }
        }

        float cmA = -1e30f, cmB = -1e30f;
#pragma unroll
        for (int nt = 0; nt < 16; ++nt) {
            uchar2 dA = *(const uchar2*)(drowA + j0 + nt * 8 + tg * 2);
            uchar2 dB = *(const uchar2*)(drowB + j0 + nt * 8 + tg * 2);
            acc_s[nt][0] += btab[dA.x];
            acc_s[nt][1] += btab[dA.y];
            acc_s[nt][2] += btab[dB.x];
            acc_s[nt][3] += btab[dB.y];
            cmA = fmaxf(cmA, fmaxf(acc_s[nt][0], acc_s[nt][1]));
            cmB = fmaxf(cmB, fmaxf(acc_s[nt][2], acc_s[nt][3]));
        }
        cmA = fmaxf(cmA, __shfl_xor_sync(0xFFFFFFFFu, cmA, 1));
        cmA = fmaxf(cmA, __shfl_xor_sync(0xFFFFFFFFu, cmA, 2));
        cmB = fmaxf(cmB, __shfl_xor_sync(0xFFFFFFFFu, cmB, 1));
        cmB = fmaxf(cmB, __shfl_xor_sync(0xFFFFFFFFu, cmB, 2));

        float mAn = fmaxf(mA, cmA), mBn = fmaxf(mB, cmB);
        float corrA = ex2f((mA - mAn) * L2E);
        float corrB = ex2f((mB - mBn) * L2E);
        mA = mAn; mB = mBn;

        uint32_t ph0[16], ph1[16];
        float lsA = 0.f, lsB = 0.f;
#pragma unroll
        for (int nt = 0; nt < 16; ++nt) {
            float p0 = ex2f((acc_s[nt][0] - mA) * L2E);
            float p1 = ex2f((acc_s[nt][1] - mA) * L2E);
            float p2 = ex2f((acc_s[nt][2] - mB) * L2E);
            float p3 = ex2f((acc_s[nt][3] - mB) * L2E);
            lsA += p0 + p1; lsB += p2 + p3;
            ph0[nt] = packh(p0, p1);
            ph1[nt] = packh(p2, p3);
        }
        lsA += __shfl_xor_sync(0xFFFFFFFFu, lsA, 1);
        lsA += __shfl_xor_sync(0xFFFFFFFFu, lsA, 2);
        lsB += __shfl_xor_sync(0xFFFFFFFFu, lsB, 1);
        lsB += __shfl_xor_sync(0xFFFFFFFFu, lsB, 2);
        lA = lA * corrA + lsA;
        lB = lB * corrB + lsB;

#pragma unroll
        for (int nto = 0; nto < 4; ++nto) {
            acc_o[nto][0] *= corrA; acc_o[nto][1] *= corrA;
            acc_o[nto][2] *= corrB; acc_o[nto][3] *= corrB;
        }

#pragma unroll
        for (int kc = 0; kc < 8; ++kc) {
            uint32_t a0 = ph0[2 * kc], a1 = ph1[2 * kc], a2 = ph0[2 * kc + 1], a3 = ph1[2 * kc + 1];
#pragma unroll
            for (int nto = 0; nto < 4; ++nto) {
                int idx = (nto * 8 + r) * 68 + kc * 8 + tg;
                uint32_t b0h = VH[idx], b1h = VH[idx + 4];
                uint32_t b0l = VL[idx], b1l = VL[idx + 4];
                MMAH(acc_o[nto], a0, a1, a2, a3, b0h, b1h);
                MMAH(acc_o[nto], a0, a1, a2, a3, b0l, b1l);
            }
        }
        __syncthreads();
    }

    float invA = 1.f / lA, invB = 1.f / lB;
#pragma unroll
    for (int nto = 0; nto < 4; ++nto) {
        int col = h * HDIM + nto * 8 + tg * 2;
        *(uint32_t*)(oh + (size_t)(g * MM + rowA) * HH + col) =
            packh(acc_o[nto][0] * invA, acc_o[nto][1] * invA);
        *(uint32_t*)(oh + (size_t)(g * MM + rowB) * HH + col) =
            packh(acc_o[nto][2] * invB, acc_o[nto][3] * invB);
    }
}

// ---------------- LayerNorm (up to 3 summed inputs) ----------------
__launch_bounds__(256)
__global__ void ln_kernel(const float* __restrict__ a, const float* __restrict__ b,
                          const float* __restrict__ c, const float* __restrict__ gam,
                          const float* __restrict__ bet, float* __restrict__ out,
                          __half* __restrict__ oh) {
    int row = blockIdx.x, t = threadIdx.x;
    size_t idx = (size_t)row * HH + t;
    float v = a[idx];
    if (b) v += b[idx];
    if (c) v += c[idx];
    float s = v, s2 = v * v;
#pragma unroll
    for (int o = 16; o; o >>= 1) {
        s  += __shfl_xor_sync(0xFFFFFFFFu, s, o);
        s2 += __shfl_xor_sync(0xFFFFFFFFu, s2, o);
    }
    __shared__ float sh1[8], sh2[8];
    int w = t >> 5, ln = t & 31;
    if (ln == 0) { sh1[w] = s; sh2[w] = s2; }
    __syncthreads();
    if (w == 0) {
        s  = (ln < 8) ? sh1[ln] : 0.f;
        s2 = (ln < 8) ? sh2[ln] : 0.f;
#pragma unroll
        for (int o = 4; o; o >>= 1) {
            s  += __shfl_xor_sync(0xFFFFFFFFu, s, o);
            s2 += __shfl_xor_sync(0xFFFFFFFFu, s2, o);
        }
        if (ln == 0) { sh1[0] = s; sh2[0] = s2; }
    }
    __syncthreads();
    float mean = sh1[0] * (1.f / HH);
    float var  = sh2[0] * (1.f / HH) - mean * mean;
    float rr = (v - mean) * rsqrtf(var + 1e-5f) * gam[t] + bet[t];
    out[idx] = rr;
    if (oh) oh[idx] = __float2half(rr);
}

// ---------------- host ----------------
static void* sym(const void* s) { void* p = nullptr; cudaGetSymbolAddress(&p, s); return p; }

extern "C" void kernel_launch(void* const* d_in, const int* in_sizes, int n_in,
                              void* d_out, int out_size) {
    const float* x      = (const float*)d_in[0];
    const float* gcn_w  = (const float*)d_in[1];
    const float* gcn_b  = (const float*)d_in[2];
    const float* qkv_w  = (const float*)d_in[3];
    const float* qkv_b  = (const float*)d_in[4];
    const float* proj_w = (const float*)d_in[5];
    const float* proj_b = (const float*)d_in[6];
    const float* ln1_g  = (const float*)d_in[7];
    const float* ln1_b  = (const float*)d_in[8];
    const float* ln2_g  = (const float*)d_in[9];
    const float* ln2_b  = (const float*)d_in[10];
    const float* ffn1_w = (const float*)d_in[11];
    const float* ffn1_b = (const float*)d_in[12];
    const float* ffn2_w = (const float*)d_in[13];
    const float* ffn2_b = (const float*)d_in[14];
    const float* bias_e = (const float*)d_in[15];
    const float* oln1_g = (const float*)d_in[16];
    const float* oln1_b = (const float*)d_in[17];
    const float* oln2_g = (const float*)d_in[18];
    const float* oln2_b = (const float*)d_in[19];
    const float* offn1_w= (const float*)d_in[20];
    const float* offn1_b= (const float*)d_in[21];
    const float* offn2_w= (const float*)d_in[22];
    const float* offn2_b= (const float*)d_in[23];
    const int*   ei     = (const int*)d_in[24];
    int E = in_sizes[24] / 2;

    float*    p_deg  = (float*)sym(g_deg);
    float*    p_dinv = (float*)sym(g_dinv);
    float*    p_xw   = (float*)sym(g_xw);
    float*    p_xl   = (float*)sym(g_xl);
    uint32_t* p_adj  = (uint32_t*)sym(g_adj);
    unsigned char* p_dist = (unsigned char*)sym(g_dist);
    float*    p_qkv  = (float*)sym(g_qkv);
    float*    p_tmp  = (float*)sym(g_tmp);
    float*    p_h1   = (float*)sym(g_h1);
    float*    p_h2   = (float*)sym(g_h2);
    float*    p_y    = (float*)sym(g_y);
    __half* x_h   = (__half*)sym(g_x_h);
    __half* at_h  = (__half*)sym(g_at_h);
    __half* h1_h  = (__half*)sym(g_h1_h);
    __half* y_h   = (__half*)sym(g_y_h);
    __half* mid_h = (__half*)sym(g_mid_h);
    __half* q_h   = (__half*)sym(g_q_h);
    __half* k_h   = (__half*)sym(g_k_h);
    __half* k_l   = (__half*)sym(g_k_l);
    __half* vt_h  = (__half*)sym(g_vt_h);
    __half* vt_l  = (__half*)sym(g_vt_l);
    __half* whi   = (__half*)sym(g_whi);
    __half* wlo   = (__half*)sym(g_wlo);
    float* out = (float*)d_out;

    const int SMEM = 61440;
    const int ASMEM = 75776;
    cudaFuncSetAttribute(gemm_f16<0,0,0,0>, cudaFuncAttributeMaxDynamicSharedMemorySize, SMEM);
    cudaFuncSetAttribute(gemm_f16<0,1,0,0>, cudaFuncAttributeMaxDynamicSharedMemorySize, SMEM);
    cudaFuncSetAttribute(gemm_f16<1,0,1,0>, cudaFuncAttributeMaxDynamicSharedMemorySize, SMEM);
    cudaFuncSetAttribute(gemm_f16<0,0,0,1>, cudaFuncAttributeMaxDynamicSharedMemorySize, SMEM);
    cudaFuncSetAttribute(attn_mma, cudaFuncAttributeMaxDynamicSharedMemorySize, ASMEM);
    cudaFuncSetAttribute(spd_kernel, cudaFuncAttributeMaxDynamicSharedMemorySize, MM * 33 * 4);

    // launches 1-3: prep; launch 4 = QKV GEMM (ncu profiles the 4th launch)
    splitx<<<(NN * HH / 4 + 255) / 256, 256>>>((const float4*)x, x_h, NN * HH / 4);
    splitw<<<(344064 + 255) / 256, 256>>>((const float4*)gcn_w, (const float4*)qkv_w,
        (const float4*)proj_w, (const float4*)ffn1_w, (const float4*)ffn2_w,
        (const float4*)offn1_w, (const float4*)offn2_w, whi, wlo);
    zero_prep<<<(GG * MM * 32 + 255) / 256, 256>>>(p_deg, p_adj);
    gemm_f16<0,0,0,0><<<dim3(NN/128, QKVD/128), 256, SMEM>>>(x_h, whi + OFF_QKV, wlo + OFF_QKV,
        qkv_b, nullptr, p_qkv, nullptr, nullptr, nullptr, HH, QKVD);

    // --- graph prep + GCN branch (fused dinv epilogue) ---
    edge_prep<<<(E + 255) / 256, 256>>>(ei, E, p_deg, p_adj);
    dinv_kernel<<<NN / 256, 256>>>(p_deg, p_dinv);
    gemm_f16<0,0,0,1><<<dim3(NN/128, HH/128), 256, SMEM>>>(x_h, whi + OFF_GCN, wlo + OFF_GCN,
        gcn_b, nullptr, p_xl, nullptr, p_xw, p_dinv, HH, HH);
    edge_scatter<<<(E * 64 + 255) / 256, 256>>>(ei, E, p_xw, p_dinv, p_xl);
    spd_kernel<<<64, 128, MM * 33 * 4>>>(p_adj, p_dist);

    // --- Graphormer layer ---
    qkv_prep<<<NN / 64, 256>>>(p_qkv, q_h, k_h, k_l, vt_h, vt_l);
    attn_mma<<<dim3(GG * NHEADS, MM / 128), 256, ASMEM>>>(q_h, k_h, k_l, vt_h, vt_l,
        p_dist, bias_e, at_h);
    gemm_f16<0,1,0,0><<<dim3(NN/128, HH/128), 256, SMEM>>>(at_h, whi + OFF_PROJ, wlo + OFF_PROJ,
        proj_b, x, p_tmp, nullptr, nullptr, nullptr, HH, HH);
    ln_kernel<<<NN, 256>>>(p_tmp, nullptr, nullptr, ln1_g, ln1_b, p_h1, h1_h);
    gemm_f16<1,0,1,0><<<dim3(NN/128, FFND/128), 256, SMEM>>>(h1_h, whi + OFF_FFN1, wlo + OFF_FFN1,
        ffn1_b, nullptr, nullptr, mid_h, nullptr, nullptr, HH, FFND);
    gemm_f16<0,1,0,0><<<dim3(NN/128, HH/128), 256, SMEM>>>(mid_h, whi + OFF_FFN2, wlo + OFF_FFN2,
        ffn2_b, p_h1, p_tmp, nullptr, nullptr, nullptr, FFND, HH);
    ln_kernel<<<NN, 256>>>(p_tmp, nullptr, nullptr, ln2_g, ln2_b, p_h2, nullptr);

    // --- GPS combine + outer FFN ---
    ln_kernel<<<NN, 256>>>(x, p_xl, p_h2, oln1_g, oln1_b, p_y, y_h);
    gemm_f16<1,0,1,0><<<dim3(NN/128, FFND/128), 256, SMEM>>>(y_h, whi + OFF_OFFN1, wlo + OFF_OFFN1,
        offn1_b, nullptr, nullptr, mid_h, nullptr, nullptr, HH, FFND);
    gemm_f16<0,1,0,0><<<dim3(NN/128, HH/128), 256, SMEM>>>(mid_h, whi + OFF_OFFN2, wlo + OFF_OFFN2,
        offn2_b, p_y, p_tmp, nullptr, nullptr, nullptr, FFND, HH);
    ln_kernel<<<NN, 256>>>(p_tmp, nullptr, nullptr, oln2_g, oln2_b, out, nullptr);
}

// round 7
// speedup vs baseline: 1.0770x; 1.0149x over previous
#include <cuda_runtime.h>
#include <cuda_fp16.h>
#include <cstdint>
#include <math.h>

#define GG 8
#define MM 1024
#define NN 8192
#define HH 256
#define NHEADS 8
#define HDIM 32
#define FFND 1024
#define QKVD 768

// ---------------- scratch ----------------
__device__ float    g_dinv[NN];
__device__ float    g_xw  [NN * HH];
__device__ float    g_xl  [NN * HH];
__device__ uint32_t g_adj [GG * MM * 32];
__device__ unsigned char g_dist[(size_t)GG * MM * MM];
__device__ float    g_qkv [(size_t)NN * QKVD];
__device__ float    g_tmp [NN * HH];
__device__ float    g_h1  [NN * HH];
__device__ float    g_h2  [NN * HH];
__device__ float    g_y   [NN * HH];
__device__ int      g_cnt [NN];
__device__ int      g_base[NN];
__device__ int      g_fillp[NN];
__device__ int      g_esrc[262144];

#define AL16 __align__(16)
__device__ AL16 __half g_x_h [NN * HH];
__device__ AL16 __half g_at_h[NN * HH];
__device__ AL16 __half g_h1_h[NN * HH];
__device__ AL16 __half g_y_h [NN * HH];
__device__ AL16 __half g_mid_h[(size_t)NN * FFND];
__device__ AL16 __half g_q_h [NN * HH];
__device__ AL16 __half g_k_h [NN * HH], g_k_l [NN * HH];
__device__ AL16 __half g_vt_h[GG * NHEADS * HDIM * MM], g_vt_l[GG * NHEADS * HDIM * MM];
__device__ AL16 __half g_whi[1376256], g_wlo[1376256];
#define OFF_GCN   0
#define OFF_QKV   65536
#define OFF_PROJ  262144
#define OFF_FFN1  327680
#define OFF_FFN2  589824
#define OFF_OFFN1 851968
#define OFF_OFFN2 1114112

// ---------------- helpers ----------------
__device__ __forceinline__ uint32_t packh(float a, float b) {
    uint32_t r;
    asm("cvt.rn.f16x2.f32 %0, %1, %2;" : "=r"(r) : "f"(b), "f"(a));
    return r;
}
__device__ __forceinline__ float ex2f(float x) {
    float y; asm("ex2.approx.f32 %0, %1;" : "=f"(y) : "f"(x)); return y;
}
__device__ __forceinline__ void split2(float a, float b, uint32_t& hi, uint32_t& lo) {
    uint32_t h = packh(a, b);
    __half2 h2 = *reinterpret_cast<__half2*>(&h);
    float2 f2 = __half22float2(h2);
    hi = h;
    lo = packh(a - f2.x, b - f2.y);
}
#define CP16(dst, src) asm volatile("cp.async.cg.shared.global [%0], [%1], 16;\n" :: "r"(dst), "l"(src))
#define MMAH(d, a0, a1, a2, a3, b0, b1) \
    asm volatile("mma.sync.aligned.m16n8k16.row.col.f32.f16.f16.f32 " \
                 "{%0,%1,%2,%3}, {%4,%5,%6,%7}, {%8,%9}, {%0,%1,%2,%3};" \
                 : "+f"(d[0]), "+f"(d[1]), "+f"(d[2]), "+f"(d[3]) \
                 : "r"(a0), "r"(a1), "r"(a2), "r"(a3), "r"(b0), "r"(b1))
#define LDSM4(r0, r1, r2, r3, addr) \
    asm volatile("ldmatrix.sync.aligned.m8n8.x4.shared.b16 {%0,%1,%2,%3}, [%4];" \
                 : "=r"(r0), "=r"(r1), "=r"(r2), "=r"(r3) : "r"(addr))

// ---------------- splits ----------------
__global__ void splitx(const float4* __restrict__ in, __half* __restrict__ hi, int n4) {
    int i = blockIdx.x * blockDim.x + threadIdx.x;
    if (i >= n4) return;
    float4 v = in[i];
    *(uint2*)(hi + i * 4) = make_uint2(packh(v.x, v.y), packh(v.z, v.w));
}
__global__ void splitw(const float4* w0, const float4* w1, const float4* w2, const float4* w3,
                       const float4* w4, const float4* w5, const float4* w6,
                       __half* __restrict__ hi, __half* __restrict__ lo) {
    int i = blockIdx.x * blockDim.x + threadIdx.x;
    if (i >= 344064) return;
    const float4* src; int base;
    if      (i < 16384)  { src = w0; base = 0; }
    else if (i < 65536)  { src = w1; base = 16384; }
    else if (i < 81920)  { src = w2; base = 65536; }
    else if (i < 147456) { src = w3; base = 81920; }
    else if (i < 212992) { src = w4; base = 147456; }
    else if (i < 278528) { src = w5; base = 212992; }
    else                 { src = w6; base = 278528; }
    float4 v = src[i - base];
    uint32_t h0, l0, h1, l1;
    split2(v.x, v.y, h0, l0);
    split2(v.z, v.w, h1, l1);
    *(uint2*)(hi + (size_t)i * 4) = make_uint2(h0, h1);
    *(uint2*)(lo + (size_t)i * 4) = make_uint2(l0, l1);
}

// ---------------- graph prep ----------------
__global__ void zero_prep(int* __restrict__ cnt, uint32_t* __restrict__ adj) {
    int i = blockIdx.x * blockDim.x + threadIdx.x;
    if (i < GG * MM * 32) adj[i] = 0u;
    if (i < NN) cnt[i] = 0;
}
__global__ void edge_prep(const int* __restrict__ ei, int E, int* __restrict__ cnt,
                          uint32_t* __restrict__ adj) {
    int e = blockIdx.x * blockDim.x + threadIdx.x;
    if (e >= E) return;
    int s = ei[e], d = ei[E + e];
    atomicAdd(&cnt[d], 1);
    if (s == d || (s >> 10) != (d >> 10)) return;
    int g = s >> 10, ls = s & 1023, ld = d & 1023;
    atomicOr(&adj[((size_t)g * MM + ls) * 32 + (ld >> 5)], 1u << (ld & 31));
    atomicOr(&adj[((size_t)g * MM + ld) * 32 + (ls >> 5)], 1u << (ls & 31));
}
// exclusive scan of cnt[8192], one block of 1024 threads
__global__ void scan_kernel(const int* __restrict__ cnt, int* __restrict__ base,
                            int* __restrict__ fillp, float* __restrict__ dinv) {
    __shared__ int wsum[32];
    int t = threadIdx.x;
    int v[8]; int s = 0;
#pragma unroll
    for (int k = 0; k < 8; ++k) { v[k] = s; s += cnt[t * 8 + k]; }
    int lane = t & 31, w = t >> 5;
    int tot = s, sc = s;
#pragma unroll
    for (int o = 1; o < 32; o <<= 1) {
        int n = __shfl_up_sync(0xFFFFFFFFu, sc, o);
        if (lane >= o) sc += n;
    }
    if (lane == 31) wsum[w] = sc;
    __syncthreads();
    if (w == 0) {
        int x = wsum[lane];
#pragma unroll
        for (int o = 1; o < 32; o <<= 1) {
            int n = __shfl_up_sync(0xFFFFFFFFu, x, o);
            if (lane >= o) x += n;
        }
        wsum[lane] = x;
    }
    __syncthreads();
    int excl = sc - tot + (w > 0 ? wsum[w - 1] : 0);
#pragma unroll
    for (int k = 0; k < 8; ++k) {
        int idx = t * 8 + k;
        int b = excl + v[k];
        base[idx] = b;
        fillp[idx] = b;
        dinv[idx] = rsqrtf((float)cnt[idx] + 1.0f);
    }
}
__global__ void fill_edges(const int* __restrict__ ei, int E, int* __restrict__ fillp,
                           int* __restrict__ esrc) {
    int e = blockIdx.x * blockDim.x + threadIdx.x;
    if (e >= E) return;
    int s = ei[e], d = ei[E + e];
    int pos = atomicAdd(&fillp[d], 1);
    esrc[pos] = s;
}
// GCN aggregation: gather per destination node (no atomics)
__launch_bounds__(256)
__global__ void gcn_gather(const float* __restrict__ xw, const float* __restrict__ dinv,
                           const int* __restrict__ base, const int* __restrict__ cnt,
                           const int* __restrict__ esrc, const float* __restrict__ gcn_b,
                           float* __restrict__ xl) {
    int node = blockIdx.x * 4 + (threadIdx.x >> 6);
    int c4 = (threadIdx.x & 63) * 4;
    float dd = dinv[node];
    float4 v0 = *(const float4*)&xw[(size_t)node * HH + c4];
    float4 acc;
    acc.x = dd * v0.x; acc.y = dd * v0.y; acc.z = dd * v0.z; acc.w = dd * v0.w;
    int b0 = __ldg(&base[node]);
    int n  = __ldg(&cnt[node]);
    for (int k = 0; k < n; ++k) {
        int s = __ldg(&esrc[b0 + k]);
        float ws = __ldg(&dinv[s]);
        float4 v = *(const float4*)&xw[(size_t)s * HH + c4];
        acc.x += ws * v.x; acc.y += ws * v.y; acc.z += ws * v.z; acc.w += ws * v.w;
    }
    float4 bia = *(const float4*)&gcn_b[c4];
    float4 o;
    o.x = dd * acc.x + bia.x; o.y = dd * acc.y + bia.y;
    o.z = dd * acc.z + bia.z; o.w = dd * acc.w + bia.w;
    *(float4*)&xl[(size_t)node * HH + c4] = o;
}

// ---------------- SPD bitset BFS: 16 CTAs/graph x 64 threads ----------------
__launch_bounds__(64)
__global__ void spd_kernel(const uint32_t* __restrict__ adj, unsigned char* __restrict__ dist) {
    extern __shared__ uint32_t adj_sh[];   // [1024][33]
    int g = blockIdx.x >> 4;
    const uint32_t* ga = adj + (size_t)g * MM * 32;
    for (int idx = threadIdx.x; idx < MM * 32; idx += blockDim.x) {
        int r = idx >> 5, w = idx & 31;
        adj_sh[r * 33 + w] = ga[idx];
    }
    __syncthreads();

    int i = (blockIdx.x & 15) * 64 + threadIdx.x;
    unsigned char* drow = dist + ((size_t)g * MM + i) * MM;

    uint32_t reach[32], frontier[32];
#pragma unroll
    for (int w = 0; w < 32; ++w) {
        uint32_t a = adj_sh[i * 33 + w];
        reach[w] = a; frontier[w] = a;
    }
#pragma unroll
    for (int w = 0; w < 32; ++w) {
        uint32_t f = frontier[w];
        uint32_t* dp = (uint32_t*)(drow + w * 32);
#pragma unroll
        for (int q = 0; q < 8; ++q) {
            uint32_t nib = (f >> (q * 4)) & 0xF;
            uint32_t word = 0x06060606u;
            if (nib & 1) word = (word & 0xFFFFFF00u) | 0x01u;
            if (nib & 2) word = (word & 0xFFFF00FFu) | 0x0100u;
            if (nib & 4) word = (word & 0xFF00FFFFu) | 0x010000u;
            if (nib & 8) word = (word & 0x00FFFFFFu) | 0x01000000u;
            dp[q] = word;
        }
    }
    drow[i] = 0;
    reach[i >> 5] |= 1u << (i & 31);

    for (int d = 2; d <= 5; ++d) {
        uint32_t nw[32];
#pragma unroll
        for (int w = 0; w < 32; ++w) nw[w] = 0u;
        for (int w = 0; w < 32; ++w) {
            uint32_t f = frontier[w];
            while (f) {
                int b = __ffs((int)f) - 1;
                f &= f - 1;
                const uint32_t* aj = &adj_sh[(w * 32 + b) * 33];
#pragma unroll
                for (int ww = 0; ww < 32; ++ww) nw[ww] |= aj[ww];
            }
        }
        uint32_t any = 0;
        uint32_t rep = (uint32_t)d * 0x01010101u;
#pragma unroll
        for (int w = 0; w < 32; ++w) {
            uint32_t newly = nw[w] & ~reach[w];
            frontier[w] = newly;
            reach[w] |= newly;
            any |= newly;
            if (newly) {
                uint32_t* dp = (uint32_t*)(drow + w * 32);
#pragma unroll
                for (int q = 0; q < 8; ++q) {
                    uint32_t nib = (newly >> (q * 4)) & 0xF;
                    if (nib) {
                        uint32_t m = ((nib & 1) ? 0xFFu : 0u) | ((nib & 2) ? 0xFF00u : 0u)
                                   | ((nib & 4) ? 0xFF0000u : 0u) | ((nib & 8) ? 0xFF000000u : 0u);
                        dp[q] = (dp[q] & ~m) | (rep & m);
                    }
                }
            }
        }
        if (!any) break;
    }
}

// ---------------- fp16 GEMM with ldmatrix: C = A @ W^T ----------------
template <int GELU, int RES, int OUTF16>
__launch_bounds__(256, 2)
__global__ void gemm_f16(const __half* __restrict__ Ag, const __half* __restrict__ Whg,
                         const __half* __restrict__ Wlg,
                         const float* __restrict__ bias, const float* __restrict__ res,
                         float* __restrict__ C, __half* __restrict__ Ch, int K, int F) {
    extern __shared__ unsigned char smp[];
    const int STG = 30720;
    int m0 = blockIdx.x * 128, f0 = blockIdx.y * 128;
    int tid = threadIdx.x, lane = tid & 31, warp = tid >> 5;
    int g = lane >> 2, tg = lane & 3;
    int wm = (warp >> 2) * 64, wn = (warp & 3) * 32;
    uint32_t smem_base = (uint32_t)__cvta_generic_to_shared(smp);

    // ldmatrix per-lane offsets
    uint32_t aOff = (uint32_t)(wm + (lane & 15)) * 80 + (uint32_t)(lane >> 4) * 16;
    uint32_t bOff = (uint32_t)(wn + ((lane >> 4) << 3) + (lane & 7)) * 80
                  + (uint32_t)((lane >> 3) & 1) * 16;

    float acc[4][4][4];
#pragma unroll
    for (int a = 0; a < 4; ++a)
#pragma unroll
        for (int b = 0; b < 4; ++b)
#pragma unroll
            for (int c = 0; c < 4; ++c) acc[a][b][c] = 0.f;

    auto load_stage = [&](int s, int k0) {
        uint32_t db = smem_base + s * STG;
        const __half* srcs[3] = {
            Ag + (size_t)m0 * K + k0, Whg + (size_t)f0 * K + k0, Wlg + (size_t)f0 * K + k0 };
#pragma unroll
        for (int arr = 0; arr < 3; ++arr) {
            const __half* bp = srcs[arr];
            uint32_t ab = db + arr * 10240;
#pragma unroll
            for (int c = 0; c < 2; ++c) {
                int t = tid + c * 256;
                int row = t >> 2, ch = t & 3;
                CP16(ab + row * 80 + ch * 16, bp + (size_t)row * K + ch * 8);
            }
        }
        asm volatile("cp.async.commit_group;\n" ::);
    };

    int nk = K >> 5;
    load_stage(0, 0);
    for (int kc = 0; kc < nk; ++kc) {
        if (kc + 1 < nk) {
            load_stage((kc + 1) & 1, (kc + 1) << 5);
            asm volatile("cp.async.wait_group 1;\n" ::);
        } else {
            asm volatile("cp.async.wait_group 0;\n" ::);
        }
        __syncthreads();

        uint32_t stg = smem_base + (kc & 1) * STG;
        uint32_t aB  = stg + aOff;
        uint32_t whB = stg + 10240 + bOff;
        uint32_t wlB = stg + 20480 + bOff;
#pragma unroll
        for (int ks = 0; ks < 2; ++ks) {
            uint32_t bh[4][2], bl[4][2];
            LDSM4(bh[0][0], bh[0][1], bh[1][0], bh[1][1], whB + ks * 32);
            LDSM4(bh[2][0], bh[2][1], bh[3][0], bh[3][1], whB + 1280 + ks * 32);
            LDSM4(bl[0][0], bl[0][1], bl[1][0], bl[1][1], wlB + ks * 32);
            LDSM4(bl[2][0], bl[2][1], bl[3][0], bl[3][1], wlB + 1280 + ks * 32);
#pragma unroll
            for (int mt = 0; mt < 4; ++mt) {
                uint32_t a0, a1, a2, a3;
                LDSM4(a0, a1, a2, a3, aB + mt * 1280 + ks * 32);
#pragma unroll
                for (int nt = 0; nt < 4; ++nt) {
                    MMAH(acc[mt][nt], a0, a1, a2, a3, bh[nt][0], bh[nt][1]);
                    MMAH(acc[mt][nt], a0, a1, a2, a3, bl[nt][0], bl[nt][1]);
                }
            }
        }
        __syncthreads();
    }

#pragma unroll
    for (int mt = 0; mt < 4; ++mt) {
#pragma unroll
        for (int half = 0; half < 2; ++half) {
            int row = m0 + wm + mt * 16 + g + half * 8;
#pragma unroll
            for (int nt = 0; nt < 4; ++nt) {
                int col = f0 + wn + nt * 8 + tg * 2;
                float v0 = acc[mt][nt][half * 2 + 0];
                float v1 = acc[mt][nt][half * 2 + 1];
                if (bias) { v0 += bias[col]; v1 += bias[col + 1]; }
                if (GELU) { v0 = v0 * normcdff(v0); v1 = v1 * normcdff(v1); }
                if (RES)  { v0 += res[(size_t)row * F + col]; v1 += res[(size_t)row * F + col + 1]; }
                if (OUTF16) {
                    *(uint32_t*)(Ch + (size_t)row * F + col) = packh(v0, v1);
                } else {
                    float2 o; o.x = v0; o.y = v1;
                    *(float2*)(C + (size_t)row * F + col) = o;
                }
            }
        }
    }
}

// ---------------- qkv prepass ----------------
__launch_bounds__(256)
__global__ void qkv_prep(const float* __restrict__ qkv,
                         __half* __restrict__ qh,
                         __half* __restrict__ kh, __half* __restrict__ kl,
                         __half* __restrict__ vth, __half* __restrict__ vtl) {
    __shared__ float vsm[64][33];
    int nb = blockIdx.x * 64;
    int g = nb >> 10;
    int jb = nb & 1023;
    int tid = threadIdx.x;
    const float scale = 0.17677669529663687f;

#pragma unroll
    for (int it = 0; it < 32; ++it) {
        int flat = tid + it * 256;
        int row = flat >> 7, c4 = flat & 127;
        int node = nb + row;
        float4 v = *(const float4*)&qkv[(size_t)node * QKVD + c4 * 4];
        int c = c4 * 4;
        if (c < 256) {
            *(uint2*)(qh + (size_t)node * HH + c) =
                make_uint2(packh(v.x * scale, v.y * scale), packh(v.z * scale, v.w * scale));
        } else {
            uint32_t h0, l0, h1, l1;
            split2(v.x, v.y, h0, l0);
            split2(v.z, v.w, h1, l1);
            *(uint2*)(kh + (size_t)node * HH + c - 256) = make_uint2(h0, h1);
            *(uint2*)(kl + (size_t)node * HH + c - 256) = make_uint2(l0, l1);
        }
    }

    for (int h = 0; h < NHEADS; ++h) {
        __syncthreads();
#pragma unroll
        for (int it = 0; it < 2; ++it) {
            int flat = tid + it * 256;
            int row = flat >> 3, c4 = flat & 7;
            float4 v = *(const float4*)&qkv[(size_t)(nb + row) * QKVD + 512 + h * 32 + c4 * 4];
            vsm[row][c4 * 4 + 0] = v.x;
            vsm[row][c4 * 4 + 1] = v.y;
            vsm[row][c4 * 4 + 2] = v.z;
            vsm[row][c4 * 4 + 3] = v.w;
        }
        __syncthreads();
        int d = tid >> 3, j0 = (tid & 7) * 8;
        uint32_t hw[4], lw[4];
#pragma unroll
        for (int p = 0; p < 4; ++p) {
            float a = vsm[j0 + p * 2 + 0][d];
            float b = vsm[j0 + p * 2 + 1][d];
            split2(a, b, hw[p], lw[p]);
        }
        size_t off = ((size_t)(g * NHEADS + h) * HDIM + d) * MM + jb + j0;
        *(uint4*)(vth + off) = make_uint4(hw[0], hw[1], hw[2], hw[3]);
        *(uint4*)(vtl + off) = make_uint4(lw[0], lw[1], lw[2], lw[3]);
    }
}

// ---------------- flash attention (fp16 A-single / B-dual) ----------------
__launch_bounds__(256)
__global__ void attn_mma(const __half* __restrict__ qh,
                         const __half* __restrict__ kh, const __half* __restrict__ kl,
                         const __half* __restrict__ vth, const __half* __restrict__ vtl,
                         const unsigned char* __restrict__ dist, const float* __restrict__ bias_emb,
                         __half* __restrict__ oh) {
    extern __shared__ unsigned char smp[];
    const int STG = 37888;
    __shared__ float btab[8];
    int gh = blockIdx.x;
    int g = gh >> 3, h = gh & 7;
    int i0 = blockIdx.y * 128;
    int tid = threadIdx.x, lane = tid & 31, warp = tid >> 5;
    int r = lane >> 2, tg = lane & 3;
    if (tid < 7) btab[tid] = bias_emb[tid];
    uint32_t sb = (uint32_t)__cvta_generic_to_shared(smp);
    const float L2E = 1.44269504f;

    int rowA = i0 + warp * 16 + r;
    int rowB = rowA + 8;
    uint32_t qf[2][4];
#pragma unroll
    for (int kc = 0; kc < 2; ++kc) {
        size_t baseA = (size_t)(g * MM + rowA) * HH + h * HDIM + kc * 16 + tg * 2;
        size_t baseB = (size_t)(g * MM + rowB) * HH + h * HDIM + kc * 16 + tg * 2;
        qf[kc][0] = *(const uint32_t*)(qh + baseA);
        qf[kc][1] = *(const uint32_t*)(qh + baseB);
        qf[kc][2] = *(const uint32_t*)(qh + baseA + 8);
        qf[kc][3] = *(const uint32_t*)(qh + baseB + 8);
    }

    float acc_o[4][4];
#pragma unroll
    for (int a = 0; a < 4; ++a)
#pragma unroll
        for (int b = 0; b < 4; ++b) acc_o[a][b] = 0.f;
    float mA = -1e30f, mB = -1e30f, lA = 0.f, lB = 0.f;

    const unsigned char* drowA = dist + ((size_t)(g * MM + rowA)) * MM;
    const unsigned char* drowB = dist + ((size_t)(g * MM + rowB)) * MM;

    auto load_stage = [&](int s, int j0) {
        uint32_t db = sb + s * STG;
#pragma unroll
        for (int c = 0; c < 2; ++c) {
            int t = tid + c * 256;
            int row = t >> 2, ch = t & 3;
            const __half* src = kh + (size_t)(g * MM + j0 + row) * HH + h * HDIM + ch * 8;
            CP16(db + row * 80 + ch * 16, src);
            const __half* srcl = kl + (size_t)(g * MM + j0 + row) * HH + h * HDIM + ch * 8;
            CP16(db + 10240 + row * 80 + ch * 16, srcl);
        }
#pragma unroll
        for (int c = 0; c < 2; ++c) {
            int t = tid + c * 256;
            int row = t >> 4, ch = t & 15;
            size_t off = ((size_t)(gh) * HDIM + row) * MM + j0 + ch * 8;
            CP16(db + 20480 + row * 272 + ch * 16, vth + off);
            CP16(db + 29184 + row * 272 + ch * 16, vtl + off);
        }
        asm volatile("cp.async.commit_group;\n" ::);
    };

    load_stage(0, 0);
    for (int ch = 0; ch < 8; ++ch) {
        int j0 = ch * 128;
        if (ch < 7) {
            load_stage((ch + 1) & 1, j0 + 128);
            asm volatile("cp.async.wait_group 1;\n" ::);
        } else {
            asm volatile("cp.async.wait_group 0;\n" ::);
        }
        __syncthreads();

        const uint32_t* KH = (const uint32_t*)(smp + (ch & 1) * STG);
        const uint32_t* KL = KH + 2560;
        const uint32_t* VH = KH + 5120;
        const uint32_t* VL = VH + 2176;

        float acc_s[16][4];
#pragma unroll
        for (int nt = 0; nt < 16; ++nt)
#pragma unroll
            for (int c = 0; c < 4; ++c) acc_s[nt][c] = 0.f;
#pragma unroll
        for (int kc = 0; kc < 2; ++kc) {
#pragma unroll
            for (int nt = 0; nt < 16; ++nt) {
                int idx = (nt * 8 + r) * 20 + kc * 8 + tg;
                uint32_t b0h = KH[idx], b1h = KH[idx + 4];
                uint32_t b0l = KL[idx], b1l = KL[idx + 4];
                MMAH(acc_s[nt], qf[kc][0], qf[kc][1], qf[kc][2], qf[kc][3], b0h, b1h);
                MMAH(acc_s[nt], qf[kc][0], qf[kc][1], qf[kc][2], qf[kc][3], b0l, b1l);
            }
        }

        float cmA = -1e30f, cmB = -1e30f;
#pragma unroll
        for (int nt = 0; nt < 16; ++nt) {
            uchar2 dA = *(const uchar2*)(drowA + j0 + nt * 8 + tg * 2);
            uchar2 dB = *(const uchar2*)(drowB + j0 + nt * 8 + tg * 2);
            acc_s[nt][0] += btab[dA.x];
            acc_s[nt][1] += btab[dA.y];
            acc_s[nt][2] += btab[dB.x];
            acc_s[nt][3] += btab[dB.y];
            cmA = fmaxf(cmA, fmaxf(acc_s[nt][0], acc_s[nt][1]));
            cmB = fmaxf(cmB, fmaxf(acc_s[nt][2], acc_s[nt][3]));
        }
        cmA = fmaxf(cmA, __shfl_xor_sync(0xFFFFFFFFu, cmA, 1));
        cmA = fmaxf(cmA, __shfl_xor_sync(0xFFFFFFFFu, cmA, 2));
        cmB = fmaxf(cmB, __shfl_xor_sync(0xFFFFFFFFu, cmB, 1));
        cmB = fmaxf(cmB, __shfl_xor_sync(0xFFFFFFFFu, cmB, 2));

        float mAn = fmaxf(mA, cmA), mBn = fmaxf(mB, cmB);
        float corrA = ex2f((mA - mAn) * L2E);
        float corrB = ex2f((mB - mBn) * L2E);
        mA = mAn; mB = mBn;

        uint32_t ph0[16], ph1[16];
        float lsA = 0.f, lsB = 0.f;
#pragma unroll
        for (int nt = 0; nt < 16; ++nt) {
            float p0 = ex2f((acc_s[nt][0] - mA) * L2E);
            float p1 = ex2f((acc_s[nt][1] - mA) * L2E);
            float p2 = ex2f((acc_s[nt][2] - mB) * L2E);
            float p3 = ex2f((acc_s[nt][3] - mB) * L2E);
            lsA += p0 + p1; lsB += p2 + p3;
            ph0[nt] = packh(p0, p1);
            ph1[nt] = packh(p2, p3);
        }
        lsA += __shfl_xor_sync(0xFFFFFFFFu, lsA, 1);
        lsA += __shfl_xor_sync(0xFFFFFFFFu, lsA, 2);
        lsB += __shfl_xor_sync(0xFFFFFFFFu, lsB, 1);
        lsB += __shfl_xor_sync(0xFFFFFFFFu, lsB, 2);
        lA = lA * corrA + lsA;
        lB = lB * corrB + lsB;

#pragma unroll
        for (int nto = 0; nto < 4; ++nto) {
            acc_o[nto][0] *= corrA; acc_o[nto][1] *= corrA;
            acc_o[nto][2] *= corrB; acc_o[nto][3] *= corrB;
        }

#pragma unroll
        for (int kc = 0; kc < 8; ++kc) {
            uint32_t a0 = ph0[2 * kc], a1 = ph1[2 * kc], a2 = ph0[2 * kc + 1], a3 = ph1[2 * kc + 1];
#pragma unroll
            for (int nto = 0; nto < 4; ++nto) {
                int idx = (nto * 8 + r) * 68 + kc * 8 + tg;
                uint32_t b0h = VH[idx], b1h = VH[idx + 4];
                uint32_t b0l = VL[idx], b1l = VL[idx + 4];
                MMAH(acc_o[nto], a0, a1, a2, a3, b0h, b1h);
                MMAH(acc_o[nto], a0, a1, a2, a3, b0l, b1l);
            }
        }
        __syncthreads();
    }

    float invA = 1.f / lA, invB = 1.f / lB;
#pragma unroll
    for (int nto = 0; nto < 4; ++nto) {
        int col = h * HDIM + nto * 8 + tg * 2;
        *(uint32_t*)(oh + (size_t)(g * MM + rowA) * HH + col) =
            packh(acc_o[nto][0] * invA, acc_o[nto][1] * invA);
        *(uint32_t*)(oh + (size_t)(g * MM + rowB) * HH + col) =
            packh(acc_o[nto][2] * invB, acc_o[nto][3] * invB);
    }
}

// ---------------- LayerNorm ----------------
__launch_bounds__(256)
__global__ void ln_kernel(const float* __restrict__ a, const float* __restrict__ b,
                          const float* __restrict__ c, const float* __restrict__ gam,
                          const float* __restrict__ bet, float* __restrict__ out,
                          __half* __restrict__ oh) {
    int row = blockIdx.x, t = threadIdx.x;
    size_t idx = (size_t)row * HH + t;
    float v = a[idx];
    if (b) v += b[idx];
    if (c) v += c[idx];
    float s = v, s2 = v * v;
#pragma unroll
    for (int o = 16; o; o >>= 1) {
        s  += __shfl_xor_sync(0xFFFFFFFFu, s, o);
        s2 += __shfl_xor_sync(0xFFFFFFFFu, s2, o);
    }
    __shared__ float sh1[8], sh2[8];
    int w = t >> 5, ln = t & 31;
    if (ln == 0) { sh1[w] = s; sh2[w] = s2; }
    __syncthreads();
    if (w == 0) {
        s  = (ln < 8) ? sh1[ln] : 0.f;
        s2 = (ln < 8) ? sh2[ln] : 0.f;
#pragma unroll
        for (int o = 4; o; o >>= 1) {
            s  += __shfl_xor_sync(0xFFFFFFFFu, s, o);
            s2 += __shfl_xor_sync(0xFFFFFFFFu, s2, o);
        }
        if (ln == 0) { sh1[0] = s; sh2[0] = s2; }
    }
    __syncthreads();
    float mean = sh1[0] * (1.f / HH);
    float var  = sh2[0] * (1.f / HH) - mean * mean;
    float rr = (v - mean) * rsqrtf(var + 1e-5f) * gam[t] + bet[t];
    out[idx] = rr;
    if (oh) oh[idx] = __float2half(rr);
}

// ---------------- host ----------------
static void* sym(const void* s) { void* p = nullptr; cudaGetSymbolAddress(&p, s); return p; }

extern "C" void kernel_launch(void* const* d_in, const int* in_sizes, int n_in,
                              void* d_out, int out_size) {
    const float* x      = (const float*)d_in[0];
    const float* gcn_w  = (const float*)d_in[1];
    const float* gcn_b  = (const float*)d_in[2];
    const float* qkv_w  = (const float*)d_in[3];
    const float* qkv_b  = (const float*)d_in[4];
    const float* proj_w = (const float*)d_in[5];
    const float* proj_b = (const float*)d_in[6];
    const float* ln1_g  = (const float*)d_in[7];
    const float* ln1_b  = (const float*)d_in[8];
    const float* ln2_g  = (const float*)d_in[9];
    const float* ln2_b  = (const float*)d_in[10];
    const float* ffn1_w = (const float*)d_in[11];
    const float* ffn1_b = (const float*)d_in[12];
    const float* ffn2_w = (const float*)d_in[13];
    const float* ffn2_b = (const float*)d_in[14];
    const float* bias_e = (const float*)d_in[15];
    const float* oln1_g = (const float*)d_in[16];
    const float* oln1_b = (const float*)d_in[17];
    const float* oln2_g = (const float*)d_in[18];
    const float* oln2_b = (const float*)d_in[19];
    const float* offn1_w= (const float*)d_in[20];
    const float* offn1_b= (const float*)d_in[21];
    const float* offn2_w= (const float*)d_in[22];
    const float* offn2_b= (const float*)d_in[23];
    const int*   ei     = (const int*)d_in[24];
    int E = in_sizes[24] / 2;

    float*    p_dinv = (float*)sym(g_dinv);
    float*    p_xw   = (float*)sym(g_xw);
    float*    p_xl   = (float*)sym(g_xl);
    uint32_t* p_adj  = (uint32_t*)sym(g_adj);
    unsigned char* p_dist = (unsigned char*)sym(g_dist);
    float*    p_qkv  = (float*)sym(g_qkv);
    float*    p_tmp  = (float*)sym(g_tmp);
    float*    p_h1   = (float*)sym(g_h1);
    float*    p_h2   = (float*)sym(g_h2);
    float*    p_y    = (float*)sym(g_y);
    int*      p_cnt  = (int*)sym(g_cnt);
    int*      p_base = (int*)sym(g_base);
    int*      p_fill = (int*)sym(g_fillp);
    int*      p_esrc = (int*)sym(g_esrc);
    __half* x_h   = (__half*)sym(g_x_h);
    __half* at_h  = (__half*)sym(g_at_h);
    __half* h1_h  = (__half*)sym(g_h1_h);
    __half* y_h   = (__half*)sym(g_y_h);
    __half* mid_h = (__half*)sym(g_mid_h);
    __half* q_h   = (__half*)sym(g_q_h);
    __half* k_h   = (__half*)sym(g_k_h);
    __half* k_l   = (__half*)sym(g_k_l);
    __half* vt_h  = (__half*)sym(g_vt_h);
    __half* vt_l  = (__half*)sym(g_vt_l);
    __half* whi   = (__half*)sym(g_whi);
    __half* wlo   = (__half*)sym(g_wlo);
    float* out = (float*)d_out;

    const int SMEM = 61440;
    const int ASMEM = 75776;
    cudaFuncSetAttribute(gemm_f16<0,0,0>, cudaFuncAttributeMaxDynamicSharedMemorySize, SMEM);
    cudaFuncSetAttribute(gemm_f16<0,1,0>, cudaFuncAttributeMaxDynamicSharedMemorySize, SMEM);
    cudaFuncSetAttribute(gemm_f16<1,0,1>, cudaFuncAttributeMaxDynamicSharedMemorySize, SMEM);
    cudaFuncSetAttribute(attn_mma, cudaFuncAttributeMaxDynamicSharedMemorySize, ASMEM);
    cudaFuncSetAttribute(spd_kernel, cudaFuncAttributeMaxDynamicSharedMemorySize, MM * 33 * 4);

    // launches 1-3 prep; launch 4 = QKV GEMM (kept in profiler slot)
    splitx<<<(NN * HH / 4 + 255) / 256, 256>>>((const float4*)x, x_h, NN * HH / 4);
    splitw<<<(344064 + 255) / 256, 256>>>((const float4*)gcn_w, (const float4*)qkv_w,
        (const float4*)proj_w, (const float4*)ffn1_w, (const float4*)ffn2_w,
        (const float4*)offn1_w, (const float4*)offn2_w, whi, wlo);
    zero_prep<<<(GG * MM * 32 + 255) / 256, 256>>>(p_cnt, p_adj);
    gemm_f16<0,0,0><<<dim3(NN/128, QKVD/128), 256, SMEM>>>(x_h, whi + OFF_QKV, wlo + OFF_QKV,
        qkv_b, nullptr, p_qkv, nullptr, HH, QKVD);

    // --- graph prep + GCN branch (gather-based, no float atomics) ---
    edge_prep<<<(E + 255) / 256, 256>>>(ei, E, p_cnt, p_adj);
    scan_kernel<<<1, 1024>>>(p_cnt, p_base, p_fill, p_dinv);
    fill_edges<<<(E + 255) / 256, 256>>>(ei, E, p_fill, p_esrc);
    gemm_f16<0,0,0><<<dim3(NN/128, HH/128), 256, SMEM>>>(x_h, whi + OFF_GCN, wlo + OFF_GCN,
        nullptr, nullptr, p_xw, nullptr, HH, HH);
    gcn_gather<<<NN / 4, 256>>>(p_xw, p_dinv, p_base, p_cnt, p_esrc, gcn_b, p_xl);
    spd_kernel<<<GG * 16, 64, MM * 33 * 4>>>(p_adj, p_dist);

    // --- Graphormer layer ---
    qkv_prep<<<NN / 64, 256>>>(p_qkv, q_h, k_h, k_l, vt_h, vt_l);
    attn_mma<<<dim3(GG * NHEADS, MM / 128), 256, ASMEM>>>(q_h, k_h, k_l, vt_h, vt_l,
        p_dist, bias_e, at_h);
    gemm_f16<0,1,0><<<dim3(NN/128, HH/128), 256, SMEM>>>(at_h, whi + OFF_PROJ, wlo + OFF_PROJ,
        proj_b, x, p_tmp, nullptr, HH, HH);
    ln_kernel<<<NN, 256>>>(p_tmp, nullptr, nullptr, ln1_g, ln1_b, p_h1, h1_h);
    gemm_f16<1,0,1><<<dim3(NN/128, FFND/128), 256, SMEM>>>(h1_h, whi + OFF_FFN1, wlo + OFF_FFN1,
        ffn1_b, nullptr, nullptr, mid_h, HH, FFND);
    gemm_f16<0,1,0><<<dim3(NN/128, HH/128), 256, SMEM>>>(mid_h, whi + OFF_FFN2, wlo + OFF_FFN2,
        ffn2_b, p_h1, p_tmp, nullptr, FFND, HH);
    ln_kernel<<<NN, 256>>>(p_tmp, nullptr, nullptr, ln2_g, ln2_b, p_h2, nullptr);

    // --- GPS combine + outer FFN ---
    ln_kernel<<<NN, 256>>>(x, p_xl, p_h2, oln1_g, oln1_b, p_y, y_h);
    gemm_f16<1,0,1><<<dim3(NN/128, FFND/128), 256, SMEM>>>(y_h, whi + OFF_OFFN1, wlo + OFF_OFFN1,
        offn1_b, nullptr, nullptr, mid_h, HH, FFND);
    gemm_f16<0,1,0><<<dim3(NN/128, HH/128), 256, SMEM>>>(mid_h, whi + OFF_OFFN2, wlo + OFF_OFFN2,
        offn2_b, p_y, p_tmp, nullptr, FFND, HH);
    ln_kernel<<<NN, 256>>>(p_tmp, nullptr, nullptr, oln2_g, oln2_b, out, nullptr);
}